// round 14
// baseline (speedup 1.0000x reference)
#include <cuda_runtime.h>
#include <cuda_bf16.h>
#include <cuda_fp16.h>
#include <cstdint>
#include <cstddef>

// Problem constants
constexpr int B_ = 8;
constexpr int N_ = 2048;
constexpr int INC = 128;
constexpr int HIDC = 256;
constexpr int OUTC = 32;
constexpr int BN = B_ * N_;

// Scratch (device globals: no allocation allowed)
__device__ __align__(16) float g_deg_inv[BN];
__device__ __align__(16) __nv_bfloat16 g_agg_hi[(size_t)BN * HIDC];  // row-major
__device__ __align__(16) __nv_bfloat16 g_agg_lo[(size_t)BN * HIDC];
__device__ __align__(16) __nv_bfloat16 g_h_hi[(size_t)BN * HIDC];    // row-major
__device__ __align__(16) __nv_bfloat16 g_h_lo[(size_t)BN * HIDC];
__device__ __align__(16) __nv_bfloat16 g_x_hi[(size_t)BN * INC];     // row-major
__device__ __align__(16) __nv_bfloat16 g_x_lo[(size_t)BN * INC];
// layer1: x^T fp16 single; layer2: reused as h^T fp16 single  [b][d][i]
__device__ __align__(16) __half g_T16[(size_t)B_ * HIDC * N_];
// Mask tiles, PRE-SWIZZLED fp16: [b][jt(32)][it(32)] x 8192 B (64j x 64i)
__device__ __align__(16) __half g_Mt[(size_t)B_ * N_ * N_];
__device__ __align__(16) __nv_bfloat16 g_W1t_hi[2 * HIDC * INC];   // [mtx][n][k]
__device__ __align__(16) __nv_bfloat16 g_W1t_lo[2 * HIDC * INC];
__device__ __align__(16) __nv_bfloat16 g_W2t_hi[2 * OUTC * HIDC];
__device__ __align__(16) __nv_bfloat16 g_W2t_lo[2 * OUTC * HIDC];

#define SWZ(off) ((off) ^ (((off) >> 3) & 0x70))

__device__ __forceinline__ uint32_t smem_u32(const void* p) {
    uint32_t a;
    asm("{ .reg .u64 t; cvta.to.shared.u64 t, %1; cvt.u32.u64 %0, t; }"
        : "=r"(a) : "l"(p));
    return a;
}
__device__ __forceinline__ void cpa16(uint32_t dst, const void* src) {
    asm volatile("cp.async.cg.shared.global [%0], [%1], 16;" :: "r"(dst), "l"(src));
}
__device__ __forceinline__ void ldsm4(uint32_t* r, uint32_t addr) {
    asm volatile("ldmatrix.sync.aligned.m8n8.x4.shared.b16 {%0,%1,%2,%3}, [%4];"
                 : "=r"(r[0]), "=r"(r[1]), "=r"(r[2]), "=r"(r[3]) : "r"(addr));
}
__device__ __forceinline__ void mma_bf16(float* c, const uint32_t* a,
                                         uint32_t b0, uint32_t b1) {
    asm volatile(
        "mma.sync.aligned.m16n8k16.row.col.f32.bf16.bf16.f32 "
        "{%0,%1,%2,%3}, {%4,%5,%6,%7}, {%8,%9}, {%0,%1,%2,%3};"
        : "+f"(c[0]), "+f"(c[1]), "+f"(c[2]), "+f"(c[3])
        : "r"(a[0]), "r"(a[1]), "r"(a[2]), "r"(a[3]), "r"(b0), "r"(b1));
}
__device__ __forceinline__ void mma_f16(float* c, const uint32_t* a,
                                        uint32_t b0, uint32_t b1) {
    asm volatile(
        "mma.sync.aligned.m16n8k16.row.col.f32.f16.f16.f32 "
        "{%0,%1,%2,%3}, {%4,%5,%6,%7}, {%8,%9}, {%0,%1,%2,%3};"
        : "+f"(c[0]), "+f"(c[1]), "+f"(c[2]), "+f"(c[3])
        : "r"(a[0]), "r"(a[1]), "r"(a[2]), "r"(a[3]), "r"(b0), "r"(b1));
}
__device__ __forceinline__ void split2(float v0, float v1, uint32_t& hw, uint32_t& lw) {
    __nv_bfloat16 h0 = __float2bfloat16(v0);
    __nv_bfloat16 h1 = __float2bfloat16(v1);
    __nv_bfloat16 l0 = __float2bfloat16(v0 - __bfloat162float(h0));
    __nv_bfloat16 l1 = __float2bfloat16(v1 - __bfloat162float(h1));
    __nv_bfloat162 hp; hp.x = h0; hp.y = h1;
    __nv_bfloat162 lp; lp.x = l0; lp.y = l1;
    hw = *reinterpret_cast<uint32_t*>(&hp);
    lw = *reinterpret_cast<uint32_t*>(&lp);
}

// ---------------------------------------------------------------------------
// Merged prep: z < 8: x transpose->fp16 + row-major bf16 hi/lo; z == 8: weights.
// ---------------------------------------------------------------------------
__global__ __launch_bounds__(256)
void prep_kernel(const float* __restrict__ src,
                 const float* __restrict__ W1l, const float* __restrict__ W1r,
                 const float* __restrict__ W2l, const float* __restrict__ W2r) {
    constexpr int C = INC;
    if (blockIdx.z == 8) {
        int base = (blockIdx.x * 2 + blockIdx.y) * 256 + threadIdx.x;
#pragma unroll 1
        for (int idx = base; idx < 2 * HIDC * INC + 2 * OUTC * HIDC; idx += 16384) {
            float v;
            __nv_bfloat16 *hi, *lo;
            int off;
            if (idx < 2 * HIDC * INC) {
                int mtx = idx >> 15, rem = idx & 32767;
                int n = rem >> 7, k = rem & 127;
                v = (mtx ? W1r : W1l)[k * HIDC + n];
                hi = g_W1t_hi; lo = g_W1t_lo; off = idx;
            } else {
                int j = idx - 2 * HIDC * INC;
                int mtx = j >> 13, rem = j & 8191;
                int n = rem >> 8, k = rem & 255;
                v = (mtx ? W2r : W2l)[k * OUTC + n];
                hi = g_W2t_hi; lo = g_W2t_lo; off = j;
            }
            __nv_bfloat16 h = __float2bfloat16(v);
            hi[off] = h;
            lo[off] = __float2bfloat16(v - __bfloat162float(h));
        }
        return;
    }

    __shared__ float sT[64][65];
    const int t = threadIdx.x;
    const int b = blockIdx.z, i0 = blockIdx.x * 64, d0 = blockIdx.y * 64;

#pragma unroll
    for (int p = 0; p < 4; ++p) {
        int e = t + p * 256;
        int row = e >> 4, c4 = e & 15;
        size_t goff = ((size_t)(b * N_ + i0 + row)) * C + d0 + c4 * 4;
        float4 v = *reinterpret_cast<const float4*>(src + goff);
        sT[row][c4 * 4 + 0] = v.x; sT[row][c4 * 4 + 1] = v.y;
        sT[row][c4 * 4 + 2] = v.z; sT[row][c4 * 4 + 3] = v.w;
        uint32_t h0, l0, h1, l1;
        split2(v.x, v.y, h0, l0);
        split2(v.z, v.w, h1, l1);
        *reinterpret_cast<uint2*>(g_x_hi + goff) = make_uint2(h0, h1);
        *reinterpret_cast<uint2*>(g_x_lo + goff) = make_uint2(l0, l1);
    }
    __syncthreads();

    const int d = t >> 2, ic = (t & 3) * 16;
    uint32_t hb[8];
#pragma unroll
    for (int q = 0; q < 8; ++q) {
        __half2 hp = __floats2half2_rn(sT[ic + q * 2][d], sT[ic + q * 2 + 1][d]);
        hb[q] = *reinterpret_cast<uint32_t*>(&hp);
    }
    size_t obase = ((size_t)(b * C + d0 + d)) * N_ + i0 + ic;
    reinterpret_cast<uint4*>(g_T16 + obase)[0] = make_uint4(hb[0], hb[1], hb[2], hb[3]);
    reinterpret_cast<uint4*>(g_T16 + obase)[1] = make_uint4(hb[4], hb[5], hb[6], hb[7]);
}

// ---------------------------------------------------------------------------
// agg1: mask conv overlapped with MMA; 3-stage; 3 CTAs/SM.
// CTA 64j x 128d; fp16 single-term with x^T.
// ---------------------------------------------------------------------------
__global__ __launch_bounds__(256, 3)
void agg1_kernel(const int* __restrict__ A) {
    extern __shared__ __align__(1024) char smem[];
    constexpr int C = INC;
    constexpr int NIT = N_ / 64;
    constexpr int STG = 24576;  // mask 8 KB | X 16 KB
    const int tid = threadIdx.x, lane = tid & 31, wid = tid >> 5;
    const int b = blockIdx.z, jt = blockIdx.x, j0 = jt * 64;
    const int jw = wid & 1, dw = wid >> 1;
    const uint32_t sb = smem_u32(smem);
    float* sdeg = reinterpret_cast<float*>(smem + 3 * STG);

    if (tid < 64) sdeg[tid] = 0.0f;

    float acc[2][4][4];
#pragma unroll
    for (int mg = 0; mg < 2; ++mg)
#pragma unroll
        for (int ng = 0; ng < 4; ++ng)
#pragma unroll
            for (int q = 0; q < 4; ++q) acc[mg][ng][q] = 0.0f;

    const int jj = tid & 63, iq = tid >> 6;  // iq: 16 i's each
    const int* Ap = A + (size_t)b * N_ * N_ + j0 + jj;
    float degloc = 0.0f;

    auto maskconv = [&](int it) {
        const int i0 = it * 64;
        char* mb = smem + (it % 3) * STG;
#pragma unroll
        for (int r = 0; r < 8; ++r) {
            int il = iq * 16 + r * 2;
            uint32_t b0 = Ap[(size_t)(i0 + il) * N_] ? 1u : 0u;
            uint32_t b1 = Ap[(size_t)(i0 + il + 1) * N_] ? 1u : 0u;
            degloc += (float)(b0 + b1);
            uint32_t mv = b0 * 0x3C00u | b1 * 0x3C000000u;
            *reinterpret_cast<uint32_t*>(
                mb + SWZ((uint32_t)(jj * 128 + il * 2))) = mv;
        }
    };
    auto issueX = [&](int it) {
        const int i0 = it * 64;
#pragma unroll
        for (int p = 0; p < 4; ++p) {
            int idx = tid + p * 256;
            int row = idx >> 3, c = idx & 7;
            cpa16(sb + (it % 3) * STG + 8192 + SWZ((uint32_t)(row * 128 + c * 16)),
                  g_T16 + ((size_t)(b * C + row)) * N_ + i0 + c * 8);
        }
        asm volatile("cp.async.commit_group;");
    };

    maskconv(0); issueX(0);
    maskconv(1); issueX(1);

#pragma unroll 1
    for (int it = 0; it < NIT; ++it) {
        if (it + 1 < NIT) {
            asm volatile("cp.async.wait_group 1;");
        } else {
            asm volatile("cp.async.wait_group 0;");
        }
        __syncthreads();  // single barrier per iteration

        if (it + 2 < NIT) { maskconv(it + 2); issueX(it + 2); }

        const uint32_t mbase = sb + (it % 3) * STG;
        const uint32_t xbase = mbase + 8192;
#pragma unroll
        for (int kk = 0; kk < 4; ++kk) {
            uint32_t a[2][4];
#pragma unroll
            for (int mg = 0; mg < 2; ++mg) {
                uint32_t addr = mbase + SWZ((uint32_t)(
                    (jw * 32 + mg * 16 + (lane & 15)) * 128 +
                    kk * 32 + (lane >> 4) * 16));
                ldsm4(a[mg], addr);
            }
            uint32_t bf[2][4];
#pragma unroll
            for (int ng = 0; ng < 2; ++ng) {
                int rowB = dw * 32 + ng * 16 + (lane & 7) + ((lane >> 4) << 3);
                uint32_t addr = xbase + SWZ((uint32_t)(
                    rowB * 128 + kk * 32 + ((lane >> 3) & 1) * 16));
                ldsm4(bf[ng], addr);
            }
#pragma unroll
            for (int mg = 0; mg < 2; ++mg)
#pragma unroll
                for (int ng = 0; ng < 2; ++ng)
#pragma unroll
                    for (int sub = 0; sub < 2; ++sub)
                        mma_f16(acc[mg][ng * 2 + sub], a[mg],
                                bf[ng][sub * 2], bf[ng][sub * 2 + 1]);
        }

        // coalesced gmem copy of this iteration's (already consumed) mask tile
        {
            const char* msrc = smem + (it % 3) * STG + tid * 32;
            uint4 v0 = *reinterpret_cast<const uint4*>(msrc);
            uint4 v1 = *reinterpret_cast<const uint4*>(msrc + 16);
            char* mdst = reinterpret_cast<char*>(g_Mt) +
                         (((size_t)(b * 32 + jt)) * 32 + it) * 8192 + tid * 32;
            *reinterpret_cast<uint4*>(mdst) = v0;
            *reinterpret_cast<uint4*>(mdst + 16) = v1;
        }
    }

    __syncthreads();
    atomicAdd(&sdeg[jj], degloc);
    __syncthreads();
    if (tid < 64) {
        float dinv = 1.0f / fmaxf(sdeg[tid], 1.0f);
        g_deg_inv[b * N_ + j0 + tid] = dinv;
        sdeg[tid] = dinv;
    }
    __syncthreads();

#pragma unroll
    for (int mg = 0; mg < 2; ++mg) {
        int jl0 = jw * 32 + mg * 16 + (lane >> 2);
        float dv0 = sdeg[jl0], dv1 = sdeg[jl0 + 8];
#pragma unroll
        for (int ng = 0; ng < 4; ++ng) {
            int d = dw * 32 + ng * 8 + (lane & 3) * 2;
            size_t ro = ((size_t)(b * N_ + j0 + jl0)) * C + d;
            uint32_t hw, lw;
            split2(acc[mg][ng][0] * dv0, acc[mg][ng][1] * dv0, hw, lw);
            *reinterpret_cast<uint32_t*>(g_agg_hi + ro) = hw;
            *reinterpret_cast<uint32_t*>(g_agg_lo + ro) = lw;
            split2(acc[mg][ng][2] * dv1, acc[mg][ng][3] * dv1, hw, lw);
            *reinterpret_cast<uint32_t*>(g_agg_hi + ro + (size_t)8 * C) = hw;
            *reinterpret_cast<uint32_t*>(g_agg_lo + ro + (size_t)8 * C) = lw;
        }
    }
}

// ---------------------------------------------------------------------------
// agg2 v6: raw pre-swizzled fp16 mask tiles; 2-stage (32 KB each) so THREE
// CTAs fit per SM. CTA 128j x 128d; fp16 single-term with h^T fp16.
// ---------------------------------------------------------------------------
__global__ __launch_bounds__(256, 3)
void agg2_kernel() {
    extern __shared__ __align__(1024) char smem[];
    constexpr int C = HIDC;
    constexpr int NIT = N_ / 64;
    constexpr int STG = 32768;  // mask 16 KB (2 jt tiles) | X 16 KB
    const int tid = threadIdx.x, lane = tid & 31, wid = tid >> 5;
    const int b = blockIdx.z, jt0 = blockIdx.x * 2, j0 = blockIdx.x * 128;
    const int d0 = blockIdx.y * 128;
    const int jw = wid & 3, dw = wid >> 2;
    const uint32_t sb = smem_u32(smem);

    float acc[2][8][4];
#pragma unroll
    for (int mg = 0; mg < 2; ++mg)
#pragma unroll
        for (int ng = 0; ng < 8; ++ng)
#pragma unroll
            for (int q = 0; q < 4; ++q) acc[mg][ng][q] = 0.0f;

    const char* Mbase = reinterpret_cast<const char*>(g_Mt) +
                        ((size_t)(b * 32 + jt0)) * 32 * 8192;

    auto fill = [&](int it) {
        const int i0 = it * 64;
        const uint32_t base = sb + (it & 1) * STG;
#pragma unroll
        for (int p = 0; p < 4; ++p) {
            int idx = tid + p * 256;
            int t = idx >> 9, off = (idx & 511) * 16;
            cpa16(base + t * 8192 + off,
                  Mbase + (size_t)t * 32 * 8192 + (size_t)it * 8192 + off);
        }
#pragma unroll
        for (int p = 0; p < 4; ++p) {
            int idx = tid + p * 256;
            int row = idx >> 3, c = idx & 7;
            cpa16(base + 16384 + SWZ((uint32_t)(row * 128 + c * 16)),
                  g_T16 + ((size_t)(b * C + d0 + row)) * N_ + i0 + c * 8);
        }
        asm volatile("cp.async.commit_group;");
    };

    fill(0);

#pragma unroll 1
    for (int it = 0; it < NIT; ++it) {
        if (it + 1 < NIT) {
            fill(it + 1);
            asm volatile("cp.async.wait_group 1;");
        } else {
            asm volatile("cp.async.wait_group 0;");
        }
        __syncthreads();

        const uint32_t mbase = sb + (it & 1) * STG;
        const uint32_t xbase = mbase + 16384;
#pragma unroll
        for (int kk = 0; kk < 4; ++kk) {
            uint32_t a[2][4];
#pragma unroll
            for (int mg = 0; mg < 2; ++mg) {
                int row = jw * 32 + mg * 16 + (lane & 15);
                uint32_t addr = mbase + (row >> 6) * 8192 + SWZ((uint32_t)(
                    (row & 63) * 128 + kk * 32 + (lane >> 4) * 16));
                ldsm4(a[mg], addr);
            }
            uint32_t bf[4][4];
#pragma unroll
            for (int ng = 0; ng < 4; ++ng) {
                int rowB = dw * 64 + ng * 16 + (lane & 7) + ((lane >> 4) << 3);
                uint32_t addr = xbase + SWZ((uint32_t)(
                    rowB * 128 + kk * 32 + ((lane >> 3) & 1) * 16));
                ldsm4(bf[ng], addr);
            }
#pragma unroll
            for (int mg = 0; mg < 2; ++mg)
#pragma unroll
                for (int ng = 0; ng < 4; ++ng)
#pragma unroll
                    for (int sub = 0; sub < 2; ++sub)
                        mma_f16(acc[mg][ng * 2 + sub], a[mg],
                                bf[ng][sub * 2], bf[ng][sub * 2 + 1]);
        }
        __syncthreads();
    }

#pragma unroll
    for (int mg = 0; mg < 2; ++mg) {
        int jl0 = jw * 32 + mg * 16 + (lane >> 2);
        float dv0 = g_deg_inv[b * N_ + j0 + jl0];
        float dv1 = g_deg_inv[b * N_ + j0 + jl0 + 8];
#pragma unroll
        for (int ng = 0; ng < 8; ++ng) {
            int d = d0 + dw * 64 + ng * 8 + (lane & 3) * 2;
            size_t ro = ((size_t)(b * N_ + j0 + jl0)) * C + d;
            uint32_t hw, lw;
            split2(acc[mg][ng][0] * dv0, acc[mg][ng][1] * dv0, hw, lw);
            *reinterpret_cast<uint32_t*>(g_agg_hi + ro) = hw;
            *reinterpret_cast<uint32_t*>(g_agg_lo + ro) = lw;
            split2(acc[mg][ng][2] * dv1, acc[mg][ng][3] * dv1, hw, lw);
            *reinterpret_cast<uint32_t*>(g_agg_hi + ro + (size_t)8 * C) = hw;
            *reinterpret_cast<uint32_t*>(g_agg_lo + ro + (size_t)8 * C) = lw;
        }
    }
}

// ---------------------------------------------------------------------------
// Dense1: per-64K-chunk {A_hi, A_lo, W_hi, W_lo}; 3 MMA combos; 4 stages.
// Epilogue: h row-major bf16 hi/lo + h^T fp16 single.
// ---------------------------------------------------------------------------
__global__ __launch_bounds__(256, 2)
void dense1_mma_kernel(const float* __restrict__ b1) {
    extern __shared__ __align__(1024) char smem[];
    constexpr int STG = 49152;  // Ah 8K | Al 8K | Bh 16K | Bl 16K
    const int tid = threadIdx.x, lane = tid & 31, wid = tid >> 5;
    const int mw = wid & 1, nw = wid >> 1;
    const int r0 = blockIdx.x * 64, c0 = blockIdx.y * 128;
    const int b = r0 >> 11, i0 = r0 & (N_ - 1);
    const uint32_t sb = smem_u32(smem);

    float acc[2][4][4];
#pragma unroll
    for (int mg = 0; mg < 2; ++mg)
#pragma unroll
        for (int nq = 0; nq < 4; ++nq)
#pragma unroll
            for (int q = 0; q < 4; ++q) acc[mg][nq][q] = 0.0f;

    auto load_stage = [&](int st, int sidx) {
        const int part = sidx >> 1, kb = (sidx & 1) * 64;
        const __nv_bfloat16* Ah = part ? g_x_hi : g_agg_hi;
        const __nv_bfloat16* Al = part ? g_x_lo : g_agg_lo;
        const __nv_bfloat16* Bh = g_W1t_hi + part * HIDC * INC;
        const __nv_bfloat16* Bl = g_W1t_lo + part * HIDC * INC;
#pragma unroll
        for (int p = 0; p < 4; ++p) {
            int idx = tid + p * 256;
            int r = idx >> 3, c = idx & 7;
            int hl = r >> 6, row = r & 63;
            cpa16(sb + st * STG + hl * 8192 + SWZ((uint32_t)(row * 128 + c * 16)),
                  (hl ? Al : Ah) + (size_t)(r0 + row) * INC + kb + c * 8);
        }
#pragma unroll
        for (int p = 0; p < 8; ++p) {
            int idx = tid + p * 256;
            int r = idx >> 3, c = idx & 7;
            int hl = r >> 7, row = r & 127;
            cpa16(sb + st * STG + 16384 + hl * 16384 +
                      SWZ((uint32_t)(row * 128 + c * 16)),
                  (hl ? Bl : Bh) + (size_t)(c0 + row) * INC + kb + c * 8);
        }
        asm volatile("cp.async.commit_group;");
    };

    load_stage(0, 0);

#pragma unroll 1
    for (int s = 0; s < 4; ++s) {
        const int cur = s & 1;
        if (s + 1 < 4) {
            load_stage(cur ^ 1, s + 1);
            asm volatile("cp.async.wait_group 1;");
        } else {
            asm volatile("cp.async.wait_group 0;");
        }
        __syncthreads();

        const uint32_t ahb = sb + cur * STG;
        const uint32_t alb = ahb + 8192;
        const uint32_t bhb = ahb + 16384;
        const uint32_t blb = ahb + 32768;
#pragma unroll
        for (int kk = 0; kk < 4; ++kk) {
            uint32_t ah[2][4], al[2][4];
#pragma unroll
            for (int mg = 0; mg < 2; ++mg) {
                uint32_t off = SWZ((uint32_t)(
                    (mw * 32 + mg * 16 + (lane & 15)) * 128 +
                    kk * 32 + (lane >> 4) * 16));
                ldsm4(ah[mg], ahb + off);
                ldsm4(al[mg], alb + off);
            }
            uint32_t bh[2][4], bl[2][4];
#pragma unroll
            for (int ng = 0; ng < 2; ++ng) {
                int rowB = nw * 32 + ng * 16 + (lane & 7) + ((lane >> 4) << 3);
                uint32_t off = SWZ((uint32_t)(
                    rowB * 128 + kk * 32 + ((lane >> 3) & 1) * 16));
                ldsm4(bh[ng], bhb + off);
                ldsm4(bl[ng], blb + off);
            }
#pragma unroll
            for (int mg = 0; mg < 2; ++mg)
#pragma unroll
                for (int ng = 0; ng < 2; ++ng)
#pragma unroll
                    for (int sub = 0; sub < 2; ++sub) {
                        float* c = acc[mg][ng * 2 + sub];
                        mma_bf16(c, ah[mg], bh[ng][sub * 2], bh[ng][sub * 2 + 1]);
                        mma_bf16(c, al[mg], bh[ng][sub * 2], bh[ng][sub * 2 + 1]);
                        mma_bf16(c, ah[mg], bl[ng][sub * 2], bl[ng][sub * 2 + 1]);
                    }
        }
        __syncthreads();
    }

#pragma unroll
    for (int mg = 0; mg < 2; ++mg) {
#pragma unroll
        for (int nq = 0; nq < 4; ++nq) {
            int dloc = nw * 32 + nq * 8 + (lane & 3) * 2;
            float2 bv = *reinterpret_cast<const float2*>(b1 + c0 + dloc);
            acc[mg][nq][0] = fmaxf(acc[mg][nq][0] + bv.x, 0.0f);
            acc[mg][nq][1] = fmaxf(acc[mg][nq][1] + bv.y, 0.0f);
            acc[mg][nq][2] = fmaxf(acc[mg][nq][2] + bv.x, 0.0f);
            acc[mg][nq][3] = fmaxf(acc[mg][nq][3] + bv.y, 0.0f);
            size_t ro = ((size_t)(r0 + mw * 32 + mg * 16 + (lane >> 2))) * HIDC +
                        c0 + dloc;
            uint32_t hw, lw;
            split2(acc[mg][nq][0], acc[mg][nq][1], hw, lw);
            *reinterpret_cast<uint32_t*>(g_h_hi + ro) = hw;
            *reinterpret_cast<uint32_t*>(g_h_lo + ro) = lw;
            split2(acc[mg][nq][2], acc[mg][nq][3], hw, lw);
            *reinterpret_cast<uint32_t*>(g_h_hi + ro + (size_t)8 * HIDC) = hw;
            *reinterpret_cast<uint32_t*>(g_h_lo + ro + (size_t)8 * HIDC) = lw;
        }
    }

    // single-pass transpose, fp16 single h^T
    float* sT = reinterpret_cast<float*>(smem);  // [64][129]
#pragma unroll
    for (int mg = 0; mg < 2; ++mg)
#pragma unroll
        for (int nq = 0; nq < 4; ++nq)
#pragma unroll
            for (int q = 0; q < 4; ++q) {
                int irow = mw * 32 + mg * 16 + (lane >> 2) + (q >> 1) * 8;
                int dl = nw * 32 + nq * 8 + (lane & 3) * 2 + (q & 1);
                sT[irow * 129 + dl] = acc[mg][nq][q];
            }
    __syncthreads();

    const int dl = tid & 127, iq = (tid >> 7) * 32;
    uint32_t hb[16];
#pragma unroll
    for (int q = 0; q < 16; ++q) {
        __half2 hp = __floats2half2_rn(sT[(iq + q * 2) * 129 + dl],
                                       sT[(iq + q * 2 + 1) * 129 + dl]);
        hb[q] = *reinterpret_cast<uint32_t*>(&hp);
    }
    size_t ob = ((size_t)(b * HIDC + c0 + dl)) * N_ + i0 + iq;
#pragma unroll
    for (int q = 0; q < 4; ++q)
        reinterpret_cast<uint4*>(g_T16 + ob)[q] =
            make_uint4(hb[q * 4], hb[q * 4 + 1], hb[q * 4 + 2], hb[q * 4 + 3]);
}

// ---------------------------------------------------------------------------
// Dense2: per-chunk {A_hi, A_lo, W_hi, W_lo} with 3 combos; 8 stages.
// ---------------------------------------------------------------------------
__global__ __launch_bounds__(256, 2)
void dense2_mma_kernel(const float* __restrict__ b2, float* __restrict__ out,
                       int write_raw) {
    extern __shared__ __align__(1024) char smem[];
    constexpr int STG = 40960;  // Ah 16K | Al 16K | Bh 4K | Bl 4K
    const int tid = threadIdx.x, lane = tid & 31, wid = tid >> 5;
    const int r0 = blockIdx.x * 128;
    const uint32_t sb = smem_u32(smem);

    float acc[4][4];
#pragma unroll
    for (int t = 0; t < 4; ++t)
#pragma unroll
        for (int q = 0; q < 4; ++q) acc[t][q] = 0.0f;

    auto load_stage = [&](int st, int sidx) {
        const int part = sidx >> 2, kb = (sidx & 3) * 64;
        const __nv_bfloat16* Ah = part ? g_h_hi : g_agg_hi;
        const __nv_bfloat16* Al = part ? g_h_lo : g_agg_lo;
        const __nv_bfloat16* Bh = g_W2t_hi + part * OUTC * HIDC;
        const __nv_bfloat16* Bl = g_W2t_lo + part * OUTC * HIDC;
#pragma unroll
        for (int p = 0; p < 8; ++p) {
            int idx = tid + p * 256;
            int r = idx >> 3, c = idx & 7;
            int hl = r >> 7, row = r & 127;
            cpa16(sb + st * STG + hl * 16384 + SWZ((uint32_t)(row * 128 + c * 16)),
                  (hl ? Al : Ah) + (size_t)(r0 + row) * HIDC + kb + c * 8);
        }
#pragma unroll
        for (int p = 0; p < 2; ++p) {
            int idx = tid + p * 256;
            int r = idx >> 3, c = idx & 7;
            int hl = r >> 5, row = r & 31;
            cpa16(sb + st * STG + 32768 + hl * 4096 +
                      SWZ((uint32_t)(row * 128 + c * 16)),
                  (hl ? Bl : Bh) + (size_t)row * HIDC + kb + c * 8);
        }
        asm volatile("cp.async.commit_group;");
    };

    load_stage(0, 0);

#pragma unroll 1
    for (int s = 0; s < 8; ++s) {
        const int cur = s & 1;
        if (s + 1 < 8) {
            load_stage(cur ^ 1, s + 1);
            asm volatile("cp.async.wait_group 1;");
        } else {
            asm volatile("cp.async.wait_group 0;");
        }
        __syncthreads();

        const uint32_t ahb = sb + cur * STG;
        const uint32_t alb = ahb + 16384;
        const uint32_t bhb = ahb + 32768;
        const uint32_t blb = ahb + 36864;
#pragma unroll
        for (int kk = 0; kk < 4; ++kk) {
            uint32_t ah[4], al[4];
            {
                uint32_t off = SWZ((uint32_t)(
                    (wid * 16 + (lane & 15)) * 128 + kk * 32 + (lane >> 4) * 16));
                ldsm4(ah, ahb + off);
                ldsm4(al, alb + off);
            }
            uint32_t bh[2][4], bl[2][4];
#pragma unroll
            for (int ng = 0; ng < 2; ++ng) {
                int rowB = ng * 16 + (lane & 7) + ((lane >> 4) << 3);
                uint32_t off = SWZ((uint32_t)(
                    rowB * 128 + kk * 32 + ((lane >> 3) & 1) * 16));
                ldsm4(bh[ng], bhb + off);
                ldsm4(bl[ng], blb + off);
            }
#pragma unroll
            for (int ng = 0; ng < 2; ++ng)
#pragma unroll
                for (int sub = 0; sub < 2; ++sub) {
                    float* c = acc[ng * 2 + sub];
                    mma_bf16(c, ah, bh[ng][sub * 2], bh[ng][sub * 2 + 1]);
                    mma_bf16(c, al, bh[ng][sub * 2], bh[ng][sub * 2 + 1]);
                    mma_bf16(c, ah, bl[ng][sub * 2], bl[ng][sub * 2 + 1]);
                }
        }
        __syncthreads();
    }

    float* sOut = reinterpret_cast<float*>(smem);
    __syncthreads();
#pragma unroll
    for (int t = 0; t < 4; ++t) {
        int d = t * 8 + (lane & 3) * 2;
        float2 bv = *reinterpret_cast<const float2*>(b2 + d);
        int row = wid * 16 + (lane >> 2);
        sOut[row * 33 + d] = acc[t][0] + bv.x;
        sOut[row * 33 + d + 1] = acc[t][1] + bv.y;
        sOut[(row + 8) * 33 + d] = acc[t][2] + bv.x;
        sOut[(row + 8) * 33 + d + 1] = acc[t][3] + bv.y;
    }
    __syncthreads();

#pragma unroll 1
    for (int rit = 0; rit < 16; ++rit) {
        int row = rit * 8 + wid;
        float v = sOut[row * 33 + lane];
        float m = v;
#pragma unroll
        for (int o = 16; o > 0; o >>= 1)
            m = fmaxf(m, __shfl_xor_sync(0xffffffffu, m, o));
        float s = expf(v - m);
#pragma unroll
        for (int o = 16; o > 0; o >>= 1)
            s += __shfl_xor_sync(0xffffffffu, s, o);
        float lsm = v - m - logf(s);
        size_t gi = (size_t)(r0 + row) * OUTC + lane;
        out[gi] = lsm;
        if (write_raw) out[(size_t)BN * OUTC + gi] = v;
    }
}

// ---------------------------------------------------------------------------
extern "C" void kernel_launch(void* const* d_in, const int* in_sizes, int n_in,
                              void* d_out, int out_size) {
    const float* x   = (const float*)d_in[0];
    const int*   A   = (const int*)d_in[1];
    const float* W1l = (const float*)d_in[2];
    const float* W1r = (const float*)d_in[3];
    const float* b1  = (const float*)d_in[4];
    const float* W2l = (const float*)d_in[5];
    const float* W2r = (const float*)d_in[6];
    const float* b2  = (const float*)d_in[7];
    float* out = (float*)d_out;
    (void)in_sizes; (void)n_in;

    const int write_raw = (out_size >= 2 * BN * OUTC) ? 1 : 0;

    constexpr int AGG1_SMEM = 3 * 24576 + 256;  // 73984 (x3 CTA = 221952)
    constexpr int AGG2_SMEM = 2 * 32768;        // 65536 (x3 CTA = 196608)
    constexpr int D1_SMEM = 2 * 49152;          // 98304
    constexpr int D2_SMEM = 2 * 40960;          // 81920
    cudaFuncSetAttribute(agg1_kernel,
                         cudaFuncAttributeMaxDynamicSharedMemorySize, AGG1_SMEM);
    cudaFuncSetAttribute(agg2_kernel,
                         cudaFuncAttributeMaxDynamicSharedMemorySize, AGG2_SMEM);
    cudaFuncSetAttribute(dense1_mma_kernel,
                         cudaFuncAttributeMaxDynamicSharedMemorySize, D1_SMEM);
    cudaFuncSetAttribute(dense2_mma_kernel,
                         cudaFuncAttributeMaxDynamicSharedMemorySize, D2_SMEM);

    prep_kernel<<<dim3(N_ / 64, INC / 64, B_ + 1), 256>>>(x, W1l, W1r, W2l, W2r);
    agg1_kernel<<<dim3(N_ / 64, 1, B_), 256, AGG1_SMEM>>>(A);
    dense1_mma_kernel<<<dim3(BN / 64, HIDC / 128), 256, D1_SMEM>>>(b1);
    agg2_kernel<<<dim3(N_ / 128, HIDC / 128, B_), 256, AGG2_SMEM>>>();
    dense2_mma_kernel<<<BN / 128, 256, D2_SMEM>>>(b2, out, write_raw);
}

// round 15
// speedup vs baseline: 1.4792x; 1.4792x over previous
#include <cuda_runtime.h>
#include <cuda_bf16.h>
#include <cuda_fp16.h>
#include <cstdint>
#include <cstddef>

// Problem constants
constexpr int B_ = 8;
constexpr int N_ = 2048;
constexpr int INC = 128;
constexpr int HIDC = 256;
constexpr int OUTC = 32;
constexpr int BN = B_ * N_;

// Scratch (device globals: no allocation allowed)
__device__ __align__(16) float g_deg_inv[BN];
__device__ __align__(16) __nv_bfloat16 g_agg_hi[(size_t)BN * HIDC];  // row-major
__device__ __align__(16) __nv_bfloat16 g_agg_lo[(size_t)BN * HIDC];
__device__ __align__(16) __nv_bfloat16 g_h_hi[(size_t)BN * HIDC];    // row-major
__device__ __align__(16) __nv_bfloat16 g_h_lo[(size_t)BN * HIDC];
__device__ __align__(16) __nv_bfloat16 g_x_hi[(size_t)BN * INC];     // row-major
__device__ __align__(16) __nv_bfloat16 g_x_lo[(size_t)BN * INC];
// layer1: x^T fp16 single; layer2: reused as h^T fp16 single  [b][d][i]
__device__ __align__(16) __half g_T16[(size_t)B_ * HIDC * N_];
// Mask tiles, PRE-SWIZZLED fp16: [b][jt(32)][it(32)] x 8192 B (64j x 64i)
__device__ __align__(16) __half g_Mt[(size_t)B_ * N_ * N_];
__device__ __align__(16) __nv_bfloat16 g_W1t_hi[2 * HIDC * INC];   // [mtx][n][k]
__device__ __align__(16) __nv_bfloat16 g_W1t_lo[2 * HIDC * INC];
__device__ __align__(16) __nv_bfloat16 g_W2t_hi[2 * OUTC * HIDC];
__device__ __align__(16) __nv_bfloat16 g_W2t_lo[2 * OUTC * HIDC];

#define SWZ(off) ((off) ^ (((off) >> 3) & 0x70))

__device__ __forceinline__ uint32_t smem_u32(const void* p) {
    uint32_t a;
    asm("{ .reg .u64 t; cvta.to.shared.u64 t, %1; cvt.u32.u64 %0, t; }"
        : "=r"(a) : "l"(p));
    return a;
}
__device__ __forceinline__ void cpa16(uint32_t dst, const void* src) {
    asm volatile("cp.async.cg.shared.global [%0], [%1], 16;" :: "r"(dst), "l"(src));
}
__device__ __forceinline__ void ldsm4(uint32_t* r, uint32_t addr) {
    asm volatile("ldmatrix.sync.aligned.m8n8.x4.shared.b16 {%0,%1,%2,%3}, [%4];"
                 : "=r"(r[0]), "=r"(r[1]), "=r"(r[2]), "=r"(r[3]) : "r"(addr));
}
__device__ __forceinline__ void mma_bf16(float* c, const uint32_t* a,
                                         uint32_t b0, uint32_t b1) {
    asm volatile(
        "mma.sync.aligned.m16n8k16.row.col.f32.bf16.bf16.f32 "
        "{%0,%1,%2,%3}, {%4,%5,%6,%7}, {%8,%9}, {%0,%1,%2,%3};"
        : "+f"(c[0]), "+f"(c[1]), "+f"(c[2]), "+f"(c[3])
        : "r"(a[0]), "r"(a[1]), "r"(a[2]), "r"(a[3]), "r"(b0), "r"(b1));
}
__device__ __forceinline__ void mma_f16(float* c, const uint32_t* a,
                                        uint32_t b0, uint32_t b1) {
    asm volatile(
        "mma.sync.aligned.m16n8k16.row.col.f32.f16.f16.f32 "
        "{%0,%1,%2,%3}, {%4,%5,%6,%7}, {%8,%9}, {%0,%1,%2,%3};"
        : "+f"(c[0]), "+f"(c[1]), "+f"(c[2]), "+f"(c[3])
        : "r"(a[0]), "r"(a[1]), "r"(a[2]), "r"(a[3]), "r"(b0), "r"(b1));
}
__device__ __forceinline__ void split2(float v0, float v1, uint32_t& hw, uint32_t& lw) {
    __nv_bfloat16 h0 = __float2bfloat16(v0);
    __nv_bfloat16 h1 = __float2bfloat16(v1);
    __nv_bfloat16 l0 = __float2bfloat16(v0 - __bfloat162float(h0));
    __nv_bfloat16 l1 = __float2bfloat16(v1 - __bfloat162float(h1));
    __nv_bfloat162 hp; hp.x = h0; hp.y = h1;
    __nv_bfloat162 lp; lp.x = l0; lp.y = l1;
    hw = *reinterpret_cast<uint32_t*>(&hp);
    lw = *reinterpret_cast<uint32_t*>(&lp);
}

// ---------------------------------------------------------------------------
// Merged prep: z < 8: x transpose->fp16 + row-major bf16 hi/lo; z == 8: weights.
// ---------------------------------------------------------------------------
__global__ __launch_bounds__(256)
void prep_kernel(const float* __restrict__ src,
                 const float* __restrict__ W1l, const float* __restrict__ W1r,
                 const float* __restrict__ W2l, const float* __restrict__ W2r) {
    constexpr int C = INC;
    if (blockIdx.z == 8) {
        int base = (blockIdx.x * 2 + blockIdx.y) * 256 + threadIdx.x;
#pragma unroll 1
        for (int idx = base; idx < 2 * HIDC * INC + 2 * OUTC * HIDC; idx += 16384) {
            float v;
            __nv_bfloat16 *hi, *lo;
            int off;
            if (idx < 2 * HIDC * INC) {
                int mtx = idx >> 15, rem = idx & 32767;
                int n = rem >> 7, k = rem & 127;
                v = (mtx ? W1r : W1l)[k * HIDC + n];
                hi = g_W1t_hi; lo = g_W1t_lo; off = idx;
            } else {
                int j = idx - 2 * HIDC * INC;
                int mtx = j >> 13, rem = j & 8191;
                int n = rem >> 8, k = rem & 255;
                v = (mtx ? W2r : W2l)[k * OUTC + n];
                hi = g_W2t_hi; lo = g_W2t_lo; off = j;
            }
            __nv_bfloat16 h = __float2bfloat16(v);
            hi[off] = h;
            lo[off] = __float2bfloat16(v - __bfloat162float(h));
        }
        return;
    }

    __shared__ float sT[64][65];
    const int t = threadIdx.x;
    const int b = blockIdx.z, i0 = blockIdx.x * 64, d0 = blockIdx.y * 64;

#pragma unroll
    for (int p = 0; p < 4; ++p) {
        int e = t + p * 256;
        int row = e >> 4, c4 = e & 15;
        size_t goff = ((size_t)(b * N_ + i0 + row)) * C + d0 + c4 * 4;
        float4 v = *reinterpret_cast<const float4*>(src + goff);
        sT[row][c4 * 4 + 0] = v.x; sT[row][c4 * 4 + 1] = v.y;
        sT[row][c4 * 4 + 2] = v.z; sT[row][c4 * 4 + 3] = v.w;
        uint32_t h0, l0, h1, l1;
        split2(v.x, v.y, h0, l0);
        split2(v.z, v.w, h1, l1);
        *reinterpret_cast<uint2*>(g_x_hi + goff) = make_uint2(h0, h1);
        *reinterpret_cast<uint2*>(g_x_lo + goff) = make_uint2(l0, l1);
    }
    __syncthreads();

    const int d = t >> 2, ic = (t & 3) * 16;
    uint32_t hb[8];
#pragma unroll
    for (int q = 0; q < 8; ++q) {
        __half2 hp = __floats2half2_rn(sT[ic + q * 2][d], sT[ic + q * 2 + 1][d]);
        hb[q] = *reinterpret_cast<uint32_t*>(&hp);
    }
    size_t obase = ((size_t)(b * C + d0 + d)) * N_ + i0 + ic;
    reinterpret_cast<uint4*>(g_T16 + obase)[0] = make_uint4(hb[0], hb[1], hb[2], hb[3]);
    reinterpret_cast<uint4*>(g_T16 + obase)[1] = make_uint4(hb[4], hb[5], hb[6], hb[7]);
}

// ---------------------------------------------------------------------------
// agg1: mask conv overlapped with MMA; 3-stage; single barrier per iteration.
// CTA 64j x 128d; fp16 single-term with x^T; writes fp16 mask tiles.
// ---------------------------------------------------------------------------
__global__ __launch_bounds__(256, 2)
void agg1_kernel(const int* __restrict__ A) {
    extern __shared__ __align__(1024) char smem[];
    constexpr int C = INC;
    constexpr int NIT = N_ / 64;
    constexpr int STG = 24576;  // mask 8 KB | X 16 KB
    const int tid = threadIdx.x, lane = tid & 31, wid = tid >> 5;
    const int b = blockIdx.z, jt = blockIdx.x, j0 = jt * 64;
    const int jw = wid & 1, dw = wid >> 1;
    const uint32_t sb = smem_u32(smem);
    float* sdeg = reinterpret_cast<float*>(smem + 3 * STG);

    if (tid < 64) sdeg[tid] = 0.0f;

    float acc[2][4][4];
#pragma unroll
    for (int mg = 0; mg < 2; ++mg)
#pragma unroll
        for (int ng = 0; ng < 4; ++ng)
#pragma unroll
            for (int q = 0; q < 4; ++q) acc[mg][ng][q] = 0.0f;

    const int jj = tid & 63, iq = tid >> 6;  // iq: 16 i's each
    const int* Ap = A + (size_t)b * N_ * N_ + j0 + jj;
    float degloc = 0.0f;

    auto maskconv = [&](int it) {
        const int i0 = it * 64;
        char* mb = smem + (it % 3) * STG;
#pragma unroll
        for (int r = 0; r < 8; ++r) {
            int il = iq * 16 + r * 2;
            uint32_t b0 = Ap[(size_t)(i0 + il) * N_] ? 1u : 0u;
            uint32_t b1 = Ap[(size_t)(i0 + il + 1) * N_] ? 1u : 0u;
            degloc += (float)(b0 + b1);
            uint32_t mv = b0 * 0x3C00u | b1 * 0x3C000000u;
            *reinterpret_cast<uint32_t*>(
                mb + SWZ((uint32_t)(jj * 128 + il * 2))) = mv;
        }
    };
    auto issueX = [&](int it) {
        const int i0 = it * 64;
#pragma unroll
        for (int p = 0; p < 4; ++p) {
            int idx = tid + p * 256;
            int row = idx >> 3, c = idx & 7;
            cpa16(sb + (it % 3) * STG + 8192 + SWZ((uint32_t)(row * 128 + c * 16)),
                  g_T16 + ((size_t)(b * C + row)) * N_ + i0 + c * 8);
        }
        asm volatile("cp.async.commit_group;");
    };

    maskconv(0); issueX(0);
    maskconv(1); issueX(1);

#pragma unroll 1
    for (int it = 0; it < NIT; ++it) {
        if (it + 1 < NIT) {
            asm volatile("cp.async.wait_group 1;");
        } else {
            asm volatile("cp.async.wait_group 0;");
        }
        __syncthreads();  // single barrier per iteration

        if (it + 2 < NIT) { maskconv(it + 2); issueX(it + 2); }

        const uint32_t mbase = sb + (it % 3) * STG;
        const uint32_t xbase = mbase + 8192;
#pragma unroll
        for (int kk = 0; kk < 4; ++kk) {
            uint32_t a[2][4];
#pragma unroll
            for (int mg = 0; mg < 2; ++mg) {
                uint32_t addr = mbase + SWZ((uint32_t)(
                    (jw * 32 + mg * 16 + (lane & 15)) * 128 +
                    kk * 32 + (lane >> 4) * 16));
                ldsm4(a[mg], addr);
            }
            uint32_t bf[2][4];
#pragma unroll
            for (int ng = 0; ng < 2; ++ng) {
                int rowB = dw * 32 + ng * 16 + (lane & 7) + ((lane >> 4) << 3);
                uint32_t addr = xbase + SWZ((uint32_t)(
                    rowB * 128 + kk * 32 + ((lane >> 3) & 1) * 16));
                ldsm4(bf[ng], addr);
            }
#pragma unroll
            for (int mg = 0; mg < 2; ++mg)
#pragma unroll
                for (int ng = 0; ng < 2; ++ng)
#pragma unroll
                    for (int sub = 0; sub < 2; ++sub)
                        mma_f16(acc[mg][ng * 2 + sub], a[mg],
                                bf[ng][sub * 2], bf[ng][sub * 2 + 1]);
        }

        // coalesced gmem copy of this iteration's (already consumed) mask tile
        {
            const char* msrc = smem + (it % 3) * STG + tid * 32;
            uint4 v0 = *reinterpret_cast<const uint4*>(msrc);
            uint4 v1 = *reinterpret_cast<const uint4*>(msrc + 16);
            char* mdst = reinterpret_cast<char*>(g_Mt) +
                         (((size_t)(b * 32 + jt)) * 32 + it) * 8192 + tid * 32;
            *reinterpret_cast<uint4*>(mdst) = v0;
            *reinterpret_cast<uint4*>(mdst + 16) = v1;
        }
    }

    __syncthreads();
    atomicAdd(&sdeg[jj], degloc);
    __syncthreads();
    if (tid < 64) {
        float dinv = 1.0f / fmaxf(sdeg[tid], 1.0f);
        g_deg_inv[b * N_ + j0 + tid] = dinv;
        sdeg[tid] = dinv;
    }
    __syncthreads();

#pragma unroll
    for (int mg = 0; mg < 2; ++mg) {
        int jl0 = jw * 32 + mg * 16 + (lane >> 2);
        float dv0 = sdeg[jl0], dv1 = sdeg[jl0 + 8];
#pragma unroll
        for (int ng = 0; ng < 4; ++ng) {
            int d = dw * 32 + ng * 8 + (lane & 3) * 2;
            size_t ro = ((size_t)(b * N_ + j0 + jl0)) * C + d;
            uint32_t hw, lw;
            split2(acc[mg][ng][0] * dv0, acc[mg][ng][1] * dv0, hw, lw);
            *reinterpret_cast<uint32_t*>(g_agg_hi + ro) = hw;
            *reinterpret_cast<uint32_t*>(g_agg_lo + ro) = lw;
            split2(acc[mg][ng][2] * dv1, acc[mg][ng][3] * dv1, hw, lw);
            *reinterpret_cast<uint32_t*>(g_agg_hi + ro + (size_t)8 * C) = hw;
            *reinterpret_cast<uint32_t*>(g_agg_lo + ro + (size_t)8 * C) = lw;
        }
    }
}

// ---------------------------------------------------------------------------
// agg2 v7: 64j x 128d tile (32-float acc -> low regs -> 3 CTAs/SM, 24 warps).
// Raw pre-swizzled fp16 mask tiles; 3-stage, single barrier per iteration.
// ---------------------------------------------------------------------------
__global__ __launch_bounds__(256, 3)
void agg2_kernel() {
    extern __shared__ __align__(1024) char smem[];
    constexpr int C = HIDC;
    constexpr int NIT = N_ / 64;
    constexpr int STG = 24576;  // mask 8 KB | X 16 KB
    const int tid = threadIdx.x, lane = tid & 31, wid = tid >> 5;
    const int b = blockIdx.z, jt = blockIdx.x, j0 = jt * 64;
    const int d0 = blockIdx.y * 128;
    const int jw = wid & 1, dw = wid >> 1;
    const uint32_t sb = smem_u32(smem);

    float acc[2][4][4];
#pragma unroll
    for (int mg = 0; mg < 2; ++mg)
#pragma unroll
        for (int ng = 0; ng < 4; ++ng)
#pragma unroll
            for (int q = 0; q < 4; ++q) acc[mg][ng][q] = 0.0f;

    const char* Mbase = reinterpret_cast<const char*>(g_Mt) +
                        ((size_t)(b * 32 + jt)) * 32 * 8192;

    auto fill = [&](int it) {
        const int i0 = it * 64;
        const uint32_t base = sb + (it % 3) * STG;
        // mask tile: raw 8 KB copy (already swizzled)
#pragma unroll
        for (int p = 0; p < 2; ++p) {
            int idx = tid + p * 256;
            cpa16(base + idx * 16, Mbase + (size_t)it * 8192 + idx * 16);
        }
        // X fp16: 128d x 64i
#pragma unroll
        for (int p = 0; p < 4; ++p) {
            int idx = tid + p * 256;
            int row = idx >> 3, c = idx & 7;
            cpa16(base + 8192 + SWZ((uint32_t)(row * 128 + c * 16)),
                  g_T16 + ((size_t)(b * C + d0 + row)) * N_ + i0 + c * 8);
        }
        asm volatile("cp.async.commit_group;");
    };

    fill(0);
    fill(1);

#pragma unroll 1
    for (int it = 0; it < NIT; ++it) {
        if (it + 1 < NIT) {
            asm volatile("cp.async.wait_group 1;");
        } else {
            asm volatile("cp.async.wait_group 0;");
        }
        __syncthreads();  // single barrier per iteration

        if (it + 2 < NIT) fill(it + 2);

        const uint32_t mbase = sb + (it % 3) * STG;
        const uint32_t xbase = mbase + 8192;
#pragma unroll
        for (int kk = 0; kk < 4; ++kk) {
            uint32_t a[2][4];
#pragma unroll
            for (int mg = 0; mg < 2; ++mg) {
                uint32_t addr = mbase + SWZ((uint32_t)(
                    (jw * 32 + mg * 16 + (lane & 15)) * 128 +
                    kk * 32 + (lane >> 4) * 16));
                ldsm4(a[mg], addr);
            }
            uint32_t bf[2][4];
#pragma unroll
            for (int ng = 0; ng < 2; ++ng) {
                int rowB = dw * 32 + ng * 16 + (lane & 7) + ((lane >> 4) << 3);
                uint32_t addr = xbase + SWZ((uint32_t)(
                    rowB * 128 + kk * 32 + ((lane >> 3) & 1) * 16));
                ldsm4(bf[ng], addr);
            }
#pragma unroll
            for (int mg = 0; mg < 2; ++mg)
#pragma unroll
                for (int ng = 0; ng < 2; ++ng)
#pragma unroll
                    for (int sub = 0; sub < 2; ++sub)
                        mma_f16(acc[mg][ng * 2 + sub], a[mg],
                                bf[ng][sub * 2], bf[ng][sub * 2 + 1]);
        }
    }

#pragma unroll
    for (int mg = 0; mg < 2; ++mg) {
        int jl0 = jw * 32 + mg * 16 + (lane >> 2);
        float dv0 = g_deg_inv[b * N_ + j0 + jl0];
        float dv1 = g_deg_inv[b * N_ + j0 + jl0 + 8];
#pragma unroll
        for (int ng = 0; ng < 4; ++ng) {
            int d = d0 + dw * 32 + ng * 8 + (lane & 3) * 2;
            size_t ro = ((size_t)(b * N_ + j0 + jl0)) * C + d;
            uint32_t hw, lw;
            split2(acc[mg][ng][0] * dv0, acc[mg][ng][1] * dv0, hw, lw);
            *reinterpret_cast<uint32_t*>(g_agg_hi + ro) = hw;
            *reinterpret_cast<uint32_t*>(g_agg_lo + ro) = lw;
            split2(acc[mg][ng][2] * dv1, acc[mg][ng][3] * dv1, hw, lw);
            *reinterpret_cast<uint32_t*>(g_agg_hi + ro + (size_t)8 * C) = hw;
            *reinterpret_cast<uint32_t*>(g_agg_lo + ro + (size_t)8 * C) = lw;
        }
    }
}

// ---------------------------------------------------------------------------
// Dense1: per-64K-chunk {A_hi, A_lo, W_hi, W_lo}; 3 MMA combos; 4 stages.
// Epilogue: h row-major bf16 hi/lo + h^T fp16 single.
// ---------------------------------------------------------------------------
__global__ __launch_bounds__(256, 2)
void dense1_mma_kernel(const float* __restrict__ b1) {
    extern __shared__ __align__(1024) char smem[];
    constexpr int STG = 49152;  // Ah 8K | Al 8K | Bh 16K | Bl 16K
    const int tid = threadIdx.x, lane = tid & 31, wid = tid >> 5;
    const int mw = wid & 1, nw = wid >> 1;
    const int r0 = blockIdx.x * 64, c0 = blockIdx.y * 128;
    const int b = r0 >> 11, i0 = r0 & (N_ - 1);
    const uint32_t sb = smem_u32(smem);

    float acc[2][4][4];
#pragma unroll
    for (int mg = 0; mg < 2; ++mg)
#pragma unroll
        for (int nq = 0; nq < 4; ++nq)
#pragma unroll
            for (int q = 0; q < 4; ++q) acc[mg][nq][q] = 0.0f;

    auto load_stage = [&](int st, int sidx) {
        const int part = sidx >> 1, kb = (sidx & 1) * 64;
        const __nv_bfloat16* Ah = part ? g_x_hi : g_agg_hi;
        const __nv_bfloat16* Al = part ? g_x_lo : g_agg_lo;
        const __nv_bfloat16* Bh = g_W1t_hi + part * HIDC * INC;
        const __nv_bfloat16* Bl = g_W1t_lo + part * HIDC * INC;
#pragma unroll
        for (int p = 0; p < 4; ++p) {
            int idx = tid + p * 256;
            int r = idx >> 3, c = idx & 7;
            int hl = r >> 6, row = r & 63;
            cpa16(sb + st * STG + hl * 8192 + SWZ((uint32_t)(row * 128 + c * 16)),
                  (hl ? Al : Ah) + (size_t)(r0 + row) * INC + kb + c * 8);
        }
#pragma unroll
        for (int p = 0; p < 8; ++p) {
            int idx = tid + p * 256;
            int r = idx >> 3, c = idx & 7;
            int hl = r >> 7, row = r & 127;
            cpa16(sb + st * STG + 16384 + hl * 16384 +
                      SWZ((uint32_t)(row * 128 + c * 16)),
                  (hl ? Bl : Bh) + (size_t)(c0 + row) * INC + kb + c * 8);
        }
        asm volatile("cp.async.commit_group;");
    };

    load_stage(0, 0);

#pragma unroll 1
    for (int s = 0; s < 4; ++s) {
        const int cur = s & 1;
        if (s + 1 < 4) {
            load_stage(cur ^ 1, s + 1);
            asm volatile("cp.async.wait_group 1;");
        } else {
            asm volatile("cp.async.wait_group 0;");
        }
        __syncthreads();

        const uint32_t ahb = sb + cur * STG;
        const uint32_t alb = ahb + 8192;
        const uint32_t bhb = ahb + 16384;
        const uint32_t blb = ahb + 32768;
#pragma unroll
        for (int kk = 0; kk < 4; ++kk) {
            uint32_t ah[2][4], al[2][4];
#pragma unroll
            for (int mg = 0; mg < 2; ++mg) {
                uint32_t off = SWZ((uint32_t)(
                    (mw * 32 + mg * 16 + (lane & 15)) * 128 +
                    kk * 32 + (lane >> 4) * 16));
                ldsm4(ah[mg], ahb + off);
                ldsm4(al[mg], alb + off);
            }
            uint32_t bh[2][4], bl[2][4];
#pragma unroll
            for (int ng = 0; ng < 2; ++ng) {
                int rowB = nw * 32 + ng * 16 + (lane & 7) + ((lane >> 4) << 3);
                uint32_t off = SWZ((uint32_t)(
                    rowB * 128 + kk * 32 + ((lane >> 3) & 1) * 16));
                ldsm4(bh[ng], bhb + off);
                ldsm4(bl[ng], blb + off);
            }
#pragma unroll
            for (int mg = 0; mg < 2; ++mg)
#pragma unroll
                for (int ng = 0; ng < 2; ++ng)
#pragma unroll
                    for (int sub = 0; sub < 2; ++sub) {
                        float* c = acc[mg][ng * 2 + sub];
                        mma_bf16(c, ah[mg], bh[ng][sub * 2], bh[ng][sub * 2 + 1]);
                        mma_bf16(c, al[mg], bh[ng][sub * 2], bh[ng][sub * 2 + 1]);
                        mma_bf16(c, ah[mg], bl[ng][sub * 2], bl[ng][sub * 2 + 1]);
                    }
        }
        __syncthreads();
    }

#pragma unroll
    for (int mg = 0; mg < 2; ++mg) {
#pragma unroll
        for (int nq = 0; nq < 4; ++nq) {
            int dloc = nw * 32 + nq * 8 + (lane & 3) * 2;
            float2 bv = *reinterpret_cast<const float2*>(b1 + c0 + dloc);
            acc[mg][nq][0] = fmaxf(acc[mg][nq][0] + bv.x, 0.0f);
            acc[mg][nq][1] = fmaxf(acc[mg][nq][1] + bv.y, 0.0f);
            acc[mg][nq][2] = fmaxf(acc[mg][nq][2] + bv.x, 0.0f);
            acc[mg][nq][3] = fmaxf(acc[mg][nq][3] + bv.y, 0.0f);
            size_t ro = ((size_t)(r0 + mw * 32 + mg * 16 + (lane >> 2))) * HIDC +
                        c0 + dloc;
            uint32_t hw, lw;
            split2(acc[mg][nq][0], acc[mg][nq][1], hw, lw);
            *reinterpret_cast<uint32_t*>(g_h_hi + ro) = hw;
            *reinterpret_cast<uint32_t*>(g_h_lo + ro) = lw;
            split2(acc[mg][nq][2], acc[mg][nq][3], hw, lw);
            *reinterpret_cast<uint32_t*>(g_h_hi + ro + (size_t)8 * HIDC) = hw;
            *reinterpret_cast<uint32_t*>(g_h_lo + ro + (size_t)8 * HIDC) = lw;
        }
    }

    // single-pass transpose, fp16 single h^T
    float* sT = reinterpret_cast<float*>(smem);  // [64][129]
#pragma unroll
    for (int mg = 0; mg < 2; ++mg)
#pragma unroll
        for (int nq = 0; nq < 4; ++nq)
#pragma unroll
            for (int q = 0; q < 4; ++q) {
                int irow = mw * 32 + mg * 16 + (lane >> 2) + (q >> 1) * 8;
                int dl = nw * 32 + nq * 8 + (lane & 3) * 2 + (q & 1);
                sT[irow * 129 + dl] = acc[mg][nq][q];
            }
    __syncthreads();

    const int dl = tid & 127, iq = (tid >> 7) * 32;
    uint32_t hb[16];
#pragma unroll
    for (int q = 0; q < 16; ++q) {
        __half2 hp = __floats2half2_rn(sT[(iq + q * 2) * 129 + dl],
                                       sT[(iq + q * 2 + 1) * 129 + dl]);
        hb[q] = *reinterpret_cast<uint32_t*>(&hp);
    }
    size_t ob = ((size_t)(b * HIDC + c0 + dl)) * N_ + i0 + iq;
#pragma unroll
    for (int q = 0; q < 4; ++q)
        reinterpret_cast<uint4*>(g_T16 + ob)[q] =
            make_uint4(hb[q * 4], hb[q * 4 + 1], hb[q * 4 + 2], hb[q * 4 + 3]);
}

// ---------------------------------------------------------------------------
// Dense2: per-chunk {A_hi, A_lo, W_hi, W_lo} with 3 combos; 8 stages.
// ---------------------------------------------------------------------------
__global__ __launch_bounds__(256, 2)
void dense2_mma_kernel(const float* __restrict__ b2, float* __restrict__ out,
                       int write_raw) {
    extern __shared__ __align__(1024) char smem[];
    constexpr int STG = 40960;  // Ah 16K | Al 16K | Bh 4K | Bl 4K
    const int tid = threadIdx.x, lane = tid & 31, wid = tid >> 5;
    const int r0 = blockIdx.x * 128;
    const uint32_t sb = smem_u32(smem);

    float acc[4][4];
#pragma unroll
    for (int t = 0; t < 4; ++t)
#pragma unroll
        for (int q = 0; q < 4; ++q) acc[t][q] = 0.0f;

    auto load_stage = [&](int st, int sidx) {
        const int part = sidx >> 2, kb = (sidx & 3) * 64;
        const __nv_bfloat16* Ah = part ? g_h_hi : g_agg_hi;
        const __nv_bfloat16* Al = part ? g_h_lo : g_agg_lo;
        const __nv_bfloat16* Bh = g_W2t_hi + part * OUTC * HIDC;
        const __nv_bfloat16* Bl = g_W2t_lo + part * OUTC * HIDC;
#pragma unroll
        for (int p = 0; p < 8; ++p) {
            int idx = tid + p * 256;
            int r = idx >> 3, c = idx & 7;
            int hl = r >> 7, row = r & 127;
            cpa16(sb + st * STG + hl * 16384 + SWZ((uint32_t)(row * 128 + c * 16)),
                  (hl ? Al : Ah) + (size_t)(r0 + row) * HIDC + kb + c * 8);
        }
#pragma unroll
        for (int p = 0; p < 2; ++p) {
            int idx = tid + p * 256;
            int r = idx >> 3, c = idx & 7;
            int hl = r >> 5, row = r & 31;
            cpa16(sb + st * STG + 32768 + hl * 4096 +
                      SWZ((uint32_t)(row * 128 + c * 16)),
                  (hl ? Bl : Bh) + (size_t)row * HIDC + kb + c * 8);
        }
        asm volatile("cp.async.commit_group;");
    };

    load_stage(0, 0);

#pragma unroll 1
    for (int s = 0; s < 8; ++s) {
        const int cur = s & 1;
        if (s + 1 < 8) {
            load_stage(cur ^ 1, s + 1);
            asm volatile("cp.async.wait_group 1;");
        } else {
            asm volatile("cp.async.wait_group 0;");
        }
        __syncthreads();

        const uint32_t ahb = sb + cur * STG;
        const uint32_t alb = ahb + 16384;
        const uint32_t bhb = ahb + 32768;
        const uint32_t blb = ahb + 36864;
#pragma unroll
        for (int kk = 0; kk < 4; ++kk) {
            uint32_t ah[4], al[4];
            {
                uint32_t off = SWZ((uint32_t)(
                    (wid * 16 + (lane & 15)) * 128 + kk * 32 + (lane >> 4) * 16));
                ldsm4(ah, ahb + off);
                ldsm4(al, alb + off);
            }
            uint32_t bh[2][4], bl[2][4];
#pragma unroll
            for (int ng = 0; ng < 2; ++ng) {
                int rowB = ng * 16 + (lane & 7) + ((lane >> 4) << 3);
                uint32_t off = SWZ((uint32_t)(
                    rowB * 128 + kk * 32 + ((lane >> 3) & 1) * 16));
                ldsm4(bh[ng], bhb + off);
                ldsm4(bl[ng], blb + off);
            }
#pragma unroll
            for (int ng = 0; ng < 2; ++ng)
#pragma unroll
                for (int sub = 0; sub < 2; ++sub) {
                    float* c = acc[ng * 2 + sub];
                    mma_bf16(c, ah, bh[ng][sub * 2], bh[ng][sub * 2 + 1]);
                    mma_bf16(c, al, bh[ng][sub * 2], bh[ng][sub * 2 + 1]);
                    mma_bf16(c, ah, bl[ng][sub * 2], bl[ng][sub * 2 + 1]);
                }
        }
        __syncthreads();
    }

    float* sOut = reinterpret_cast<float*>(smem);
    __syncthreads();
#pragma unroll
    for (int t = 0; t < 4; ++t) {
        int d = t * 8 + (lane & 3) * 2;
        float2 bv = *reinterpret_cast<const float2*>(b2 + d);
        int row = wid * 16 + (lane >> 2);
        sOut[row * 33 + d] = acc[t][0] + bv.x;
        sOut[row * 33 + d + 1] = acc[t][1] + bv.y;
        sOut[(row + 8) * 33 + d] = acc[t][2] + bv.x;
        sOut[(row + 8) * 33 + d + 1] = acc[t][3] + bv.y;
    }
    __syncthreads();

#pragma unroll 1
    for (int rit = 0; rit < 16; ++rit) {
        int row = rit * 8 + wid;
        float v = sOut[row * 33 + lane];
        float m = v;
#pragma unroll
        for (int o = 16; o > 0; o >>= 1)
            m = fmaxf(m, __shfl_xor_sync(0xffffffffu, m, o));
        float s = expf(v - m);
#pragma unroll
        for (int o = 16; o > 0; o >>= 1)
            s += __shfl_xor_sync(0xffffffffu, s, o);
        float lsm = v - m - logf(s);
        size_t gi = (size_t)(r0 + row) * OUTC + lane;
        out[gi] = lsm;
        if (write_raw) out[(size_t)BN * OUTC + gi] = v;
    }
}

// ---------------------------------------------------------------------------
extern "C" void kernel_launch(void* const* d_in, const int* in_sizes, int n_in,
                              void* d_out, int out_size) {
    const float* x   = (const float*)d_in[0];
    const int*   A   = (const int*)d_in[1];
    const float* W1l = (const float*)d_in[2];
    const float* W1r = (const float*)d_in[3];
    const float* b1  = (const float*)d_in[4];
    const float* W2l = (const float*)d_in[5];
    const float* W2r = (const float*)d_in[6];
    const float* b2  = (const float*)d_in[7];
    float* out = (float*)d_out;
    (void)in_sizes; (void)n_in;

    const int write_raw = (out_size >= 2 * BN * OUTC) ? 1 : 0;

    constexpr int AGG1_SMEM = 3 * 24576 + 256;  // 73984
    constexpr int AGG2_SMEM = 3 * 24576;        // 73728 (x3 CTA = 221184)
    constexpr int D1_SMEM = 2 * 49152;          // 98304
    constexpr int D2_SMEM = 2 * 40960;          // 81920
    cudaFuncSetAttribute(agg1_kernel,
                         cudaFuncAttributeMaxDynamicSharedMemorySize, AGG1_SMEM);
    cudaFuncSetAttribute(agg2_kernel,
                         cudaFuncAttributeMaxDynamicSharedMemorySize, AGG2_SMEM);
    cudaFuncSetAttribute(dense1_mma_kernel,
                         cudaFuncAttributeMaxDynamicSharedMemorySize, D1_SMEM);
    cudaFuncSetAttribute(dense2_mma_kernel,
                         cudaFuncAttributeMaxDynamicSharedMemorySize, D2_SMEM);

    prep_kernel<<<dim3(N_ / 64, INC / 64, B_ + 1), 256>>>(x, W1l, W1r, W2l, W2r);
    agg1_kernel<<<dim3(N_ / 64, 1, B_), 256, AGG1_SMEM>>>(A);
    dense1_mma_kernel<<<dim3(BN / 64, HIDC / 128), 256, D1_SMEM>>>(b1);
    agg2_kernel<<<dim3(N_ / 64, HIDC / 128, B_), 256, AGG2_SMEM>>>();
    dense2_mma_kernel<<<BN / 128, 256, D2_SMEM>>>(b2, out, write_raw);
}

// round 16
// speedup vs baseline: 1.5267x; 1.0322x over previous
#include <cuda_runtime.h>
#include <cuda_bf16.h>
#include <cuda_fp16.h>
#include <cstdint>
#include <cstddef>

// Problem constants
constexpr int B_ = 8;
constexpr int N_ = 2048;
constexpr int INC = 128;
constexpr int HIDC = 256;
constexpr int OUTC = 32;
constexpr int BN = B_ * N_;

// Scratch (device globals: no allocation allowed)
__device__ __align__(16) float g_deg_inv[BN];
__device__ __align__(16) __nv_bfloat16 g_agg_hi[(size_t)BN * HIDC];  // row-major
__device__ __align__(16) __nv_bfloat16 g_agg_lo[(size_t)BN * HIDC];
__device__ __align__(16) __nv_bfloat16 g_h_hi[(size_t)BN * HIDC];    // row-major
__device__ __align__(16) __nv_bfloat16 g_h_lo[(size_t)BN * HIDC];
__device__ __align__(16) __nv_bfloat16 g_x_hi[(size_t)BN * INC];     // row-major
__device__ __align__(16) __nv_bfloat16 g_x_lo[(size_t)BN * INC];
// layer1: x^T fp16 single; layer2: reused as h^T fp16 single  [b][d][i]
__device__ __align__(16) __half g_T16[(size_t)B_ * HIDC * N_];
// Bit-packed mask: [b][it(32)][j(2048)][iq(4)] uint16 (i = it*64 + iq*16 .. +15)
__device__ __align__(16) uint16_t g_Mbits[(size_t)B_ * 32 * N_ * 4];
__device__ __align__(16) __nv_bfloat16 g_W1t_hi[2 * HIDC * INC];   // [mtx][n][k]
__device__ __align__(16) __nv_bfloat16 g_W1t_lo[2 * HIDC * INC];
__device__ __align__(16) __nv_bfloat16 g_W2t_hi[2 * OUTC * HIDC];
__device__ __align__(16) __nv_bfloat16 g_W2t_lo[2 * OUTC * HIDC];

#define SWZ(off) ((off) ^ (((off) >> 3) & 0x70))

__device__ __forceinline__ uint32_t smem_u32(const void* p) {
    uint32_t a;
    asm("{ .reg .u64 t; cvta.to.shared.u64 t, %1; cvt.u32.u64 %0, t; }"
        : "=r"(a) : "l"(p));
    return a;
}
__device__ __forceinline__ void cpa16(uint32_t dst, const void* src) {
    asm volatile("cp.async.cg.shared.global [%0], [%1], 16;" :: "r"(dst), "l"(src));
}
__device__ __forceinline__ void ldsm4(uint32_t* r, uint32_t addr) {
    asm volatile("ldmatrix.sync.aligned.m8n8.x4.shared.b16 {%0,%1,%2,%3}, [%4];"
                 : "=r"(r[0]), "=r"(r[1]), "=r"(r[2]), "=r"(r[3]) : "r"(addr));
}
__device__ __forceinline__ void mma_bf16(float* c, const uint32_t* a,
                                         uint32_t b0, uint32_t b1) {
    asm volatile(
        "mma.sync.aligned.m16n8k16.row.col.f32.bf16.bf16.f32 "
        "{%0,%1,%2,%3}, {%4,%5,%6,%7}, {%8,%9}, {%0,%1,%2,%3};"
        : "+f"(c[0]), "+f"(c[1]), "+f"(c[2]), "+f"(c[3])
        : "r"(a[0]), "r"(a[1]), "r"(a[2]), "r"(a[3]), "r"(b0), "r"(b1));
}
__device__ __forceinline__ void mma_f16(float* c, const uint32_t* a,
                                        uint32_t b0, uint32_t b1) {
    asm volatile(
        "mma.sync.aligned.m16n8k16.row.col.f32.f16.f16.f32 "
        "{%0,%1,%2,%3}, {%4,%5,%6,%7}, {%8,%9}, {%0,%1,%2,%3};"
        : "+f"(c[0]), "+f"(c[1]), "+f"(c[2]), "+f"(c[3])
        : "r"(a[0]), "r"(a[1]), "r"(a[2]), "r"(a[3]), "r"(b0), "r"(b1));
}
__device__ __forceinline__ void split2(float v0, float v1, uint32_t& hw, uint32_t& lw) {
    __nv_bfloat16 h0 = __float2bfloat16(v0);
    __nv_bfloat16 h1 = __float2bfloat16(v1);
    __nv_bfloat16 l0 = __float2bfloat16(v0 - __bfloat162float(h0));
    __nv_bfloat16 l1 = __float2bfloat16(v1 - __bfloat162float(h1));
    __nv_bfloat162 hp; hp.x = h0; hp.y = h1;
    __nv_bfloat162 lp; lp.x = l0; lp.y = l1;
    hw = *reinterpret_cast<uint32_t*>(&hp);
    lw = *reinterpret_cast<uint32_t*>(&lp);
}
// Expand low 8 bits of w into 4 fp16x2 words ({0,1}); cheap mul form:
// pair(b0,b1) -> ((b0)|(b1<<16)) * 0x3C00
__device__ __forceinline__ uint4 expand8(uint32_t w) {
    uint4 r;
    r.x = ((w & 1u) | ((w & 2u) << 15)) * 0x3C00u;
    r.y = (((w >> 2) & 1u) | (((w >> 2) & 2u) << 15)) * 0x3C00u;
    r.z = (((w >> 4) & 1u) | (((w >> 4) & 2u) << 15)) * 0x3C00u;
    r.w = (((w >> 6) & 1u) | (((w >> 6) & 2u) << 15)) * 0x3C00u;
    return r;
}

// ---------------------------------------------------------------------------
// Merged prep: z < 8: x transpose->fp16 + row-major bf16 hi/lo; z == 8: weights.
// ---------------------------------------------------------------------------
__global__ __launch_bounds__(256)
void prep_kernel(const float* __restrict__ src,
                 const float* __restrict__ W1l, const float* __restrict__ W1r,
                 const float* __restrict__ W2l, const float* __restrict__ W2r) {
    constexpr int C = INC;
    if (blockIdx.z == 8) {
        int base = (blockIdx.x * 2 + blockIdx.y) * 256 + threadIdx.x;
#pragma unroll 1
        for (int idx = base; idx < 2 * HIDC * INC + 2 * OUTC * HIDC; idx += 16384) {
            float v;
            __nv_bfloat16 *hi, *lo;
            int off;
            if (idx < 2 * HIDC * INC) {
                int mtx = idx >> 15, rem = idx & 32767;
                int n = rem >> 7, k = rem & 127;
                v = (mtx ? W1r : W1l)[k * HIDC + n];
                hi = g_W1t_hi; lo = g_W1t_lo; off = idx;
            } else {
                int j = idx - 2 * HIDC * INC;
                int mtx = j >> 13, rem = j & 8191;
                int n = rem >> 8, k = rem & 255;
                v = (mtx ? W2r : W2l)[k * OUTC + n];
                hi = g_W2t_hi; lo = g_W2t_lo; off = j;
            }
            __nv_bfloat16 h = __float2bfloat16(v);
            hi[off] = h;
            lo[off] = __float2bfloat16(v - __bfloat162float(h));
        }
        return;
    }

    __shared__ float sT[64][65];
    const int t = threadIdx.x;
    const int b = blockIdx.z, i0 = blockIdx.x * 64, d0 = blockIdx.y * 64;

#pragma unroll
    for (int p = 0; p < 4; ++p) {
        int e = t + p * 256;
        int row = e >> 4, c4 = e & 15;
        size_t goff = ((size_t)(b * N_ + i0 + row)) * C + d0 + c4 * 4;
        float4 v = *reinterpret_cast<const float4*>(src + goff);
        sT[row][c4 * 4 + 0] = v.x; sT[row][c4 * 4 + 1] = v.y;
        sT[row][c4 * 4 + 2] = v.z; sT[row][c4 * 4 + 3] = v.w;
        uint32_t h0, l0, h1, l1;
        split2(v.x, v.y, h0, l0);
        split2(v.z, v.w, h1, l1);
        *reinterpret_cast<uint2*>(g_x_hi + goff) = make_uint2(h0, h1);
        *reinterpret_cast<uint2*>(g_x_lo + goff) = make_uint2(l0, l1);
    }
    __syncthreads();

    const int d = t >> 2, ic = (t & 3) * 16;
    uint32_t hb[8];
#pragma unroll
    for (int q = 0; q < 8; ++q) {
        __half2 hp = __floats2half2_rn(sT[ic + q * 2][d], sT[ic + q * 2 + 1][d]);
        hb[q] = *reinterpret_cast<uint32_t*>(&hp);
    }
    size_t obase = ((size_t)(b * C + d0 + d)) * N_ + i0 + ic;
    reinterpret_cast<uint4*>(g_T16 + obase)[0] = make_uint4(hb[0], hb[1], hb[2], hb[3]);
    reinterpret_cast<uint4*>(g_T16 + obase)[1] = make_uint4(hb[4], hb[5], hb[6], hb[7]);
}

// ---------------------------------------------------------------------------
// agg1: single-barrier pipeline; mask conv (LDG A + degree + fp16 STS +
// packed-bit STG) overlapped with the MMA block. 3-stage; CTA 64j x 128d.
// ---------------------------------------------------------------------------
__global__ __launch_bounds__(256, 2)
void agg1_kernel(const int* __restrict__ A) {
    extern __shared__ __align__(1024) char smem[];
    constexpr int C = INC;
    constexpr int NIT = N_ / 64;
    constexpr int STG = 24576;  // mask 8 KB | X 16 KB
    const int tid = threadIdx.x, lane = tid & 31, wid = tid >> 5;
    const int b = blockIdx.z, jt = blockIdx.x, j0 = jt * 64;
    const int jw = wid & 1, dw = wid >> 1;
    const uint32_t sb = smem_u32(smem);
    float* sdeg = reinterpret_cast<float*>(smem + 3 * STG);

    if (tid < 64) sdeg[tid] = 0.0f;

    float acc[2][4][4];
#pragma unroll
    for (int mg = 0; mg < 2; ++mg)
#pragma unroll
        for (int ng = 0; ng < 4; ++ng)
#pragma unroll
            for (int q = 0; q < 4; ++q) acc[mg][ng][q] = 0.0f;

    const int jj = tid & 63, iq = tid >> 6;  // iq: 16 i's each
    const int* Ap = A + (size_t)b * N_ * N_ + j0 + jj;
    float degloc = 0.0f;

    auto maskconv = [&](int it) {
        const int i0 = it * 64;
        char* mb = smem + (it % 3) * STG;
        uint32_t bits = 0;
#pragma unroll
        for (int r = 0; r < 8; ++r) {
            int il = iq * 16 + r * 2;
            uint32_t b0 = Ap[(size_t)(i0 + il) * N_] ? 1u : 0u;
            uint32_t b1 = Ap[(size_t)(i0 + il + 1) * N_] ? 1u : 0u;
            bits |= (b0 << (r * 2)) | (b1 << (r * 2 + 1));
            degloc += (float)(b0 + b1);
            uint32_t mv = b0 * 0x3C00u | b1 * 0x3C000000u;
            *reinterpret_cast<uint32_t*>(
                mb + SWZ((uint32_t)(jj * 128 + il * 2))) = mv;
        }
        // layout: [b][it][j][iq]
        g_Mbits[(((size_t)(b * 32 + it)) * N_ + j0 + jj) * 4 + iq] = (uint16_t)bits;
    };
    auto issueX = [&](int it) {
        const int i0 = it * 64;
#pragma unroll
        for (int p = 0; p < 4; ++p) {
            int idx = tid + p * 256;
            int row = idx >> 3, c = idx & 7;
            cpa16(sb + (it % 3) * STG + 8192 + SWZ((uint32_t)(row * 128 + c * 16)),
                  g_T16 + ((size_t)(b * C + row)) * N_ + i0 + c * 8);
        }
        asm volatile("cp.async.commit_group;");
    };

    maskconv(0); issueX(0);
    maskconv(1); issueX(1);

#pragma unroll 1
    for (int it = 0; it < NIT; ++it) {
        if (it + 1 < NIT) {
            asm volatile("cp.async.wait_group 1;");
        } else {
            asm volatile("cp.async.wait_group 0;");
        }
        __syncthreads();  // single barrier per iteration

        if (it + 2 < NIT) { maskconv(it + 2); issueX(it + 2); }

        const uint32_t mbase = sb + (it % 3) * STG;
        const uint32_t xbase = mbase + 8192;
#pragma unroll
        for (int kk = 0; kk < 4; ++kk) {
            uint32_t a[2][4];
#pragma unroll
            for (int mg = 0; mg < 2; ++mg) {
                uint32_t addr = mbase + SWZ((uint32_t)(
                    (jw * 32 + mg * 16 + (lane & 15)) * 128 +
                    kk * 32 + (lane >> 4) * 16));
                ldsm4(a[mg], addr);
            }
            uint32_t bf[2][4];
#pragma unroll
            for (int ng = 0; ng < 2; ++ng) {
                int rowB = dw * 32 + ng * 16 + (lane & 7) + ((lane >> 4) << 3);
                uint32_t addr = xbase + SWZ((uint32_t)(
                    rowB * 128 + kk * 32 + ((lane >> 3) & 1) * 16));
                ldsm4(bf[ng], addr);
            }
#pragma unroll
            for (int mg = 0; mg < 2; ++mg)
#pragma unroll
                for (int ng = 0; ng < 2; ++ng)
#pragma unroll
                    for (int sub = 0; sub < 2; ++sub)
                        mma_f16(acc[mg][ng * 2 + sub], a[mg],
                                bf[ng][sub * 2], bf[ng][sub * 2 + 1]);
        }
    }

    __syncthreads();
    atomicAdd(&sdeg[jj], degloc);
    __syncthreads();
    if (tid < 64) {
        float dinv = 1.0f / fmaxf(sdeg[tid], 1.0f);
        g_deg_inv[b * N_ + j0 + tid] = dinv;
        sdeg[tid] = dinv;
    }
    __syncthreads();

#pragma unroll
    for (int mg = 0; mg < 2; ++mg) {
        int jl0 = jw * 32 + mg * 16 + (lane >> 2);
        float dv0 = sdeg[jl0], dv1 = sdeg[jl0 + 8];
#pragma unroll
        for (int ng = 0; ng < 4; ++ng) {
            int d = dw * 32 + ng * 8 + (lane & 3) * 2;
            size_t ro = ((size_t)(b * N_ + j0 + jl0)) * C + d;
            uint32_t hw, lw;
            split2(acc[mg][ng][0] * dv0, acc[mg][ng][1] * dv0, hw, lw);
            *reinterpret_cast<uint32_t*>(g_agg_hi + ro) = hw;
            *reinterpret_cast<uint32_t*>(g_agg_lo + ro) = lw;
            split2(acc[mg][ng][2] * dv1, acc[mg][ng][3] * dv1, hw, lw);
            *reinterpret_cast<uint32_t*>(g_agg_hi + ro + (size_t)8 * C) = hw;
            *reinterpret_cast<uint32_t*>(g_agg_lo + ro + (size_t)8 * C) = lw;
        }
    }
}

// ---------------------------------------------------------------------------
// agg2 (R12 race-fixed): CTA-resident bit mask (32 KB, preloaded once);
// expansion off critical path; X re-issue after the trailing sync.
// CTA 128j x 128d; fp16 single-term with h^T fp16.
// smem: [0,32K) bits [it(32)][j(128)][8B]; [32K,+32K) X bufs; [64K,+32K) mask bufs
// ---------------------------------------------------------------------------
__global__ __launch_bounds__(256, 2)
void agg2_kernel() {
    extern __shared__ __align__(1024) char smem[];
    constexpr int C = HIDC;
    constexpr int NIT = N_ / 64;
    constexpr uint32_t XOFF = 32768, MOFF = 65536;
    const int tid = threadIdx.x, lane = tid & 31, wid = tid >> 5;
    const int b = blockIdx.z, j0 = blockIdx.x * 128;
    const int d0 = blockIdx.y * 128;
    const int jw = wid & 3, dw = wid >> 2;
    const uint32_t sb = smem_u32(smem);

    float acc[2][8][4];
#pragma unroll
    for (int mg = 0; mg < 2; ++mg)
#pragma unroll
        for (int ng = 0; ng < 8; ++ng)
#pragma unroll
            for (int q = 0; q < 4; ++q) acc[mg][ng][q] = 0.0f;

    const int jj = tid & 127, iq2 = tid >> 7;  // iq2: 32 i's per thread

    // ---- preload CTA's bit mask: 32 its x 128 j x 8 B = 32 KB ----
    {
        const char* Mb = reinterpret_cast<const char*>(g_Mbits) +
                         ((size_t)(b * 32) * N_ + j0) * 8;
#pragma unroll
        for (int p = 0; p < 8; ++p) {
            int idx = tid + p * 256;       // 2048 chunks of 16 B
            int it = idx >> 6, c = idx & 63;
            cpa16(sb + it * 1024 + c * 16, Mb + (size_t)it * (N_ * 8) + c * 16);
        }
        asm volatile("cp.async.commit_group;");
    }

    auto issueX = [&](int stage, int it) {
        const int i0 = it * 64;
#pragma unroll
        for (int p = 0; p < 4; ++p) {
            int idx = tid + p * 256;
            int row = idx >> 3, c = idx & 7;
            cpa16(sb + XOFF + stage * 16384 + SWZ((uint32_t)(row * 128 + c * 16)),
                  g_T16 + ((size_t)(b * C + d0 + row)) * N_ + i0 + c * 8);
        }
        asm volatile("cp.async.commit_group;");
    };
    auto expand = [&](int it) {
        uint32_t w = *reinterpret_cast<const uint32_t*>(
            smem + it * 1024 + jj * 8 + iq2 * 4);
        char* mb = smem + MOFF + (it & 1) * 16384;
#pragma unroll
        for (int p = 0; p < 4; ++p) {
            uint4 v = expand8(w >> (p * 8));
            *reinterpret_cast<uint4*>(
                mb + SWZ((uint32_t)(jj * 128 + iq2 * 64 + p * 16))) = v;
        }
    };

    issueX(0, 0);                               // groups: bits, X0
    asm volatile("cp.async.wait_group 1;");     // bits arrived
    __syncthreads();
    expand(0);
    issueX(1, 1);

#pragma unroll 1
    for (int it = 0; it < NIT; ++it) {
        if (it + 1 < NIT) {
            asm volatile("cp.async.wait_group 1;");
        } else {
            asm volatile("cp.async.wait_group 0;");
        }
        __syncthreads();   // X(it) + mask(it) ready; prev compute done

        if (it + 1 < NIT) expand(it + 1);  // overlaps with MMA below

        const uint32_t mbase = sb + MOFF + (it & 1) * 16384;
        const uint32_t xbase = sb + XOFF + (it & 1) * 16384;
#pragma unroll
        for (int kk = 0; kk < 4; ++kk) {
            uint32_t a[2][4];
#pragma unroll
            for (int mg = 0; mg < 2; ++mg) {
                int row = jw * 32 + mg * 16 + (lane & 15);
                uint32_t addr = mbase + SWZ((uint32_t)(
                    row * 128 + kk * 32 + (lane >> 4) * 16));
                ldsm4(a[mg], addr);
            }
            uint32_t bf[4][4];
#pragma unroll
            for (int ng = 0; ng < 4; ++ng) {
                int rowB = dw * 64 + ng * 16 + (lane & 7) + ((lane >> 4) << 3);
                uint32_t addr = xbase + SWZ((uint32_t)(
                    rowB * 128 + kk * 32 + ((lane >> 3) & 1) * 16));
                ldsm4(bf[ng], addr);
            }
#pragma unroll
            for (int mg = 0; mg < 2; ++mg)
#pragma unroll
                for (int ng = 0; ng < 4; ++ng)
#pragma unroll
                    for (int sub = 0; sub < 2; ++sub)
                        mma_f16(acc[mg][ng * 2 + sub], a[mg],
                                bf[ng][sub * 2], bf[ng][sub * 2 + 1]);
        }
        __syncthreads();   // all reads of X buf (it&1) complete
        if (it + 2 < NIT) issueX((it + 2) & 1, it + 2);  // safe: after sync
    }

#pragma unroll
    for (int mg = 0; mg < 2; ++mg) {
        int jl0 = jw * 32 + mg * 16 + (lane >> 2);
        float dv0 = g_deg_inv[b * N_ + j0 + jl0];
        float dv1 = g_deg_inv[b * N_ + j0 + jl0 + 8];
#pragma unroll
        for (int ng = 0; ng < 8; ++ng) {
            int d = d0 + dw * 64 + ng * 8 + (lane & 3) * 2;
            size_t ro = ((size_t)(b * N_ + j0 + jl0)) * C + d;
            uint32_t hw, lw;
            split2(acc[mg][ng][0] * dv0, acc[mg][ng][1] * dv0, hw, lw);
            *reinterpret_cast<uint32_t*>(g_agg_hi + ro) = hw;
            *reinterpret_cast<uint32_t*>(g_agg_lo + ro) = lw;
            split2(acc[mg][ng][2] * dv1, acc[mg][ng][3] * dv1, hw, lw);
            *reinterpret_cast<uint32_t*>(g_agg_hi + ro + (size_t)8 * C) = hw;
            *reinterpret_cast<uint32_t*>(g_agg_lo + ro + (size_t)8 * C) = lw;
        }
    }
}

// ---------------------------------------------------------------------------
// Dense1: per-64K-chunk {A_hi, A_lo, W_hi, W_lo}; 3 MMA combos; 4 stages.
// Epilogue: h row-major bf16 hi/lo + h^T fp16 single.
// ---------------------------------------------------------------------------
__global__ __launch_bounds__(256, 2)
void dense1_mma_kernel(const float* __restrict__ b1) {
    extern __shared__ __align__(1024) char smem[];
    constexpr int STG = 49152;  // Ah 8K | Al 8K | Bh 16K | Bl 16K
    const int tid = threadIdx.x, lane = tid & 31, wid = tid >> 5;
    const int mw = wid & 1, nw = wid >> 1;
    const int r0 = blockIdx.x * 64, c0 = blockIdx.y * 128;
    const int b = r0 >> 11, i0 = r0 & (N_ - 1);
    const uint32_t sb = smem_u32(smem);

    float acc[2][4][4];
#pragma unroll
    for (int mg = 0; mg < 2; ++mg)
#pragma unroll
        for (int nq = 0; nq < 4; ++nq)
#pragma unroll
            for (int q = 0; q < 4; ++q) acc[mg][nq][q] = 0.0f;

    auto load_stage = [&](int st, int sidx) {
        const int part = sidx >> 1, kb = (sidx & 1) * 64;
        const __nv_bfloat16* Ah = part ? g_x_hi : g_agg_hi;
        const __nv_bfloat16* Al = part ? g_x_lo : g_agg_lo;
        const __nv_bfloat16* Bh = g_W1t_hi + part * HIDC * INC;
        const __nv_bfloat16* Bl = g_W1t_lo + part * HIDC * INC;
#pragma unroll
        for (int p = 0; p < 4; ++p) {
            int idx = tid + p * 256;
            int r = idx >> 3, c = idx & 7;
            int hl = r >> 6, row = r & 63;
            cpa16(sb + st * STG + hl * 8192 + SWZ((uint32_t)(row * 128 + c * 16)),
                  (hl ? Al : Ah) + (size_t)(r0 + row) * INC + kb + c * 8);
        }
#pragma unroll
        for (int p = 0; p < 8; ++p) {
            int idx = tid + p * 256;
            int r = idx >> 3, c = idx & 7;
            int hl = r >> 7, row = r & 127;
            cpa16(sb + st * STG + 16384 + hl * 16384 +
                      SWZ((uint32_t)(row * 128 + c * 16)),
                  (hl ? Bl : Bh) + (size_t)(c0 + row) * INC + kb + c * 8);
        }
        asm volatile("cp.async.commit_group;");
    };

    load_stage(0, 0);

#pragma unroll 1
    for (int s = 0; s < 4; ++s) {
        const int cur = s & 1;
        if (s + 1 < 4) {
            load_stage(cur ^ 1, s + 1);
            asm volatile("cp.async.wait_group 1;");
        } else {
            asm volatile("cp.async.wait_group 0;");
        }
        __syncthreads();

        const uint32_t ahb = sb + cur * STG;
        const uint32_t alb = ahb + 8192;
        const uint32_t bhb = ahb + 16384;
        const uint32_t blb = ahb + 32768;
#pragma unroll
        for (int kk = 0; kk < 4; ++kk) {
            uint32_t ah[2][4], al[2][4];
#pragma unroll
            for (int mg = 0; mg < 2; ++mg) {
                uint32_t off = SWZ((uint32_t)(
                    (mw * 32 + mg * 16 + (lane & 15)) * 128 +
                    kk * 32 + (lane >> 4) * 16));
                ldsm4(ah[mg], ahb + off);
                ldsm4(al[mg], alb + off);
            }
            uint32_t bh[2][4], bl[2][4];
#pragma unroll
            for (int ng = 0; ng < 2; ++ng) {
                int rowB = nw * 32 + ng * 16 + (lane & 7) + ((lane >> 4) << 3);
                uint32_t off = SWZ((uint32_t)(
                    rowB * 128 + kk * 32 + ((lane >> 3) & 1) * 16));
                ldsm4(bh[ng], bhb + off);
                ldsm4(bl[ng], blb + off);
            }
#pragma unroll
            for (int mg = 0; mg < 2; ++mg)
#pragma unroll
                for (int ng = 0; ng < 2; ++ng)
#pragma unroll
                    for (int sub = 0; sub < 2; ++sub) {
                        float* c = acc[mg][ng * 2 + sub];
                        mma_bf16(c, ah[mg], bh[ng][sub * 2], bh[ng][sub * 2 + 1]);
                        mma_bf16(c, al[mg], bh[ng][sub * 2], bh[ng][sub * 2 + 1]);
                        mma_bf16(c, ah[mg], bl[ng][sub * 2], bl[ng][sub * 2 + 1]);
                    }
        }
        __syncthreads();
    }

#pragma unroll
    for (int mg = 0; mg < 2; ++mg) {
#pragma unroll
        for (int nq = 0; nq < 4; ++nq) {
            int dloc = nw * 32 + nq * 8 + (lane & 3) * 2;
            float2 bv = *reinterpret_cast<const float2*>(b1 + c0 + dloc);
            acc[mg][nq][0] = fmaxf(acc[mg][nq][0] + bv.x, 0.0f);
            acc[mg][nq][1] = fmaxf(acc[mg][nq][1] + bv.y, 0.0f);
            acc[mg][nq][2] = fmaxf(acc[mg][nq][2] + bv.x, 0.0f);
            acc[mg][nq][3] = fmaxf(acc[mg][nq][3] + bv.y, 0.0f);
            size_t ro = ((size_t)(r0 + mw * 32 + mg * 16 + (lane >> 2))) * HIDC +
                        c0 + dloc;
            uint32_t hw, lw;
            split2(acc[mg][nq][0], acc[mg][nq][1], hw, lw);
            *reinterpret_cast<uint32_t*>(g_h_hi + ro) = hw;
            *reinterpret_cast<uint32_t*>(g_h_lo + ro) = lw;
            split2(acc[mg][nq][2], acc[mg][nq][3], hw, lw);
            *reinterpret_cast<uint32_t*>(g_h_hi + ro + (size_t)8 * HIDC) = hw;
            *reinterpret_cast<uint32_t*>(g_h_lo + ro + (size_t)8 * HIDC) = lw;
        }
    }

    // single-pass transpose, fp16 single h^T
    float* sT = reinterpret_cast<float*>(smem);  // [64][129]
#pragma unroll
    for (int mg = 0; mg < 2; ++mg)
#pragma unroll
        for (int nq = 0; nq < 4; ++nq)
#pragma unroll
            for (int q = 0; q < 4; ++q) {
                int irow = mw * 32 + mg * 16 + (lane >> 2) + (q >> 1) * 8;
                int dl = nw * 32 + nq * 8 + (lane & 3) * 2 + (q & 1);
                sT[irow * 129 + dl] = acc[mg][nq][q];
            }
    __syncthreads();

    const int dl = tid & 127, iq = (tid >> 7) * 32;
    uint32_t hb[16];
#pragma unroll
    for (int q = 0; q < 16; ++q) {
        __half2 hp = __floats2half2_rn(sT[(iq + q * 2) * 129 + dl],
                                       sT[(iq + q * 2 + 1) * 129 + dl]);
        hb[q] = *reinterpret_cast<uint32_t*>(&hp);
    }
    size_t ob = ((size_t)(b * HIDC + c0 + dl)) * N_ + i0 + iq;
#pragma unroll
    for (int q = 0; q < 4; ++q)
        reinterpret_cast<uint4*>(g_T16 + ob)[q] =
            make_uint4(hb[q * 4], hb[q * 4 + 1], hb[q * 4 + 2], hb[q * 4 + 3]);
}

// ---------------------------------------------------------------------------
// Dense2: per-chunk {A_hi, A_lo, W_hi, W_lo} with 3 combos; 8 stages.
// ---------------------------------------------------------------------------
__global__ __launch_bounds__(256, 2)
void dense2_mma_kernel(const float* __restrict__ b2, float* __restrict__ out,
                       int write_raw) {
    extern __shared__ __align__(1024) char smem[];
    constexpr int STG = 40960;  // Ah 16K | Al 16K | Bh 4K | Bl 4K
    const int tid = threadIdx.x, lane = tid & 31, wid = tid >> 5;
    const int r0 = blockIdx.x * 128;
    const uint32_t sb = smem_u32(smem);

    float acc[4][4];
#pragma unroll
    for (int t = 0; t < 4; ++t)
#pragma unroll
        for (int q = 0; q < 4; ++q) acc[t][q] = 0.0f;

    auto load_stage = [&](int st, int sidx) {
        const int part = sidx >> 2, kb = (sidx & 3) * 64;
        const __nv_bfloat16* Ah = part ? g_h_hi : g_agg_hi;
        const __nv_bfloat16* Al = part ? g_h_lo : g_agg_lo;
        const __nv_bfloat16* Bh = g_W2t_hi + part * OUTC * HIDC;
        const __nv_bfloat16* Bl = g_W2t_lo + part * OUTC * HIDC;
#pragma unroll
        for (int p = 0; p < 8; ++p) {
            int idx = tid + p * 256;
            int r = idx >> 3, c = idx & 7;
            int hl = r >> 7, row = r & 127;
            cpa16(sb + st * STG + hl * 16384 + SWZ((uint32_t)(row * 128 + c * 16)),
                  (hl ? Al : Ah) + (size_t)(r0 + row) * HIDC + kb + c * 8);
        }
#pragma unroll
        for (int p = 0; p < 2; ++p) {
            int idx = tid + p * 256;
            int r = idx >> 3, c = idx & 7;
            int hl = r >> 5, row = r & 31;
            cpa16(sb + st * STG + 32768 + hl * 4096 +
                      SWZ((uint32_t)(row * 128 + c * 16)),
                  (hl ? Bl : Bh) + (size_t)row * HIDC + kb + c * 8);
        }
        asm volatile("cp.async.commit_group;");
    };

    load_stage(0, 0);

#pragma unroll 1
    for (int s = 0; s < 8; ++s) {
        const int cur = s & 1;
        if (s + 1 < 8) {
            load_stage(cur ^ 1, s + 1);
            asm volatile("cp.async.wait_group 1;");
        } else {
            asm volatile("cp.async.wait_group 0;");
        }
        __syncthreads();

        const uint32_t ahb = sb + cur * STG;
        const uint32_t alb = ahb + 16384;
        const uint32_t bhb = ahb + 32768;
        const uint32_t blb = ahb + 36864;
#pragma unroll
        for (int kk = 0; kk < 4; ++kk) {
            uint32_t ah[4], al[4];
            {
                uint32_t off = SWZ((uint32_t)(
                    (wid * 16 + (lane & 15)) * 128 + kk * 32 + (lane >> 4) * 16));
                ldsm4(ah, ahb + off);
                ldsm4(al, alb + off);
            }
            uint32_t bh[2][4], bl[2][4];
#pragma unroll
            for (int ng = 0; ng < 2; ++ng) {
                int rowB = ng * 16 + (lane & 7) + ((lane >> 4) << 3);
                uint32_t off = SWZ((uint32_t)(
                    rowB * 128 + kk * 32 + ((lane >> 3) & 1) * 16));
                ldsm4(bh[ng], bhb + off);
                ldsm4(bl[ng], blb + off);
            }
#pragma unroll
            for (int ng = 0; ng < 2; ++ng)
#pragma unroll
                for (int sub = 0; sub < 2; ++sub) {
                    float* c = acc[ng * 2 + sub];
                    mma_bf16(c, ah, bh[ng][sub * 2], bh[ng][sub * 2 + 1]);
                    mma_bf16(c, al, bh[ng][sub * 2], bh[ng][sub * 2 + 1]);
                    mma_bf16(c, ah, bl[ng][sub * 2], bl[ng][sub * 2 + 1]);
                }
        }
        __syncthreads();
    }

    float* sOut = reinterpret_cast<float*>(smem);
    __syncthreads();
#pragma unroll
    for (int t = 0; t < 4; ++t) {
        int d = t * 8 + (lane & 3) * 2;
        float2 bv = *reinterpret_cast<const float2*>(b2 + d);
        int row = wid * 16 + (lane >> 2);
        sOut[row * 33 + d] = acc[t][0] + bv.x;
        sOut[row * 33 + d + 1] = acc[t][1] + bv.y;
        sOut[(row + 8) * 33 + d] = acc[t][2] + bv.x;
        sOut[(row + 8) * 33 + d + 1] = acc[t][3] + bv.y;
    }
    __syncthreads();

#pragma unroll 1
    for (int rit = 0; rit < 16; ++rit) {
        int row = rit * 8 + wid;
        float v = sOut[row * 33 + lane];
        float m = v;
#pragma unroll
        for (int o = 16; o > 0; o >>= 1)
            m = fmaxf(m, __shfl_xor_sync(0xffffffffu, m, o));
        float s = expf(v - m);
#pragma unroll
        for (int o = 16; o > 0; o >>= 1)
            s += __shfl_xor_sync(0xffffffffu, s, o);
        float lsm = v - m - logf(s);
        size_t gi = (size_t)(r0 + row) * OUTC + lane;
        out[gi] = lsm;
        if (write_raw) out[(size_t)BN * OUTC + gi] = v;
    }
}

// ---------------------------------------------------------------------------
extern "C" void kernel_launch(void* const* d_in, const int* in_sizes, int n_in,
                              void* d_out, int out_size) {
    const float* x   = (const float*)d_in[0];
    const int*   A   = (const int*)d_in[1];
    const float* W1l = (const float*)d_in[2];
    const float* W1r = (const float*)d_in[3];
    const float* b1  = (const float*)d_in[4];
    const float* W2l = (const float*)d_in[5];
    const float* W2r = (const float*)d_in[6];
    const float* b2  = (const float*)d_in[7];
    float* out = (float*)d_out;
    (void)in_sizes; (void)n_in;

    const int write_raw = (out_size >= 2 * BN * OUTC) ? 1 : 0;

    constexpr int AGG1_SMEM = 3 * 24576 + 256;  // 73984
    constexpr int AGG2_SMEM = 98304;            // bits 32K + X 32K + mask 32K
    constexpr int D1_SMEM = 2 * 49152;          // 98304
    constexpr int D2_SMEM = 2 * 40960;          // 81920
    cudaFuncSetAttribute(agg1_kernel,
                         cudaFuncAttributeMaxDynamicSharedMemorySize, AGG1_SMEM);
    cudaFuncSetAttribute(agg2_kernel,
                         cudaFuncAttributeMaxDynamicSharedMemorySize, AGG2_SMEM);
    cudaFuncSetAttribute(dense1_mma_kernel,
                         cudaFuncAttributeMaxDynamicSharedMemorySize, D1_SMEM);
    cudaFuncSetAttribute(dense2_mma_kernel,
                         cudaFuncAttributeMaxDynamicSharedMemorySize, D2_SMEM);

    prep_kernel<<<dim3(N_ / 64, INC / 64, B_ + 1), 256>>>(x, W1l, W1r, W2l, W2r);
    agg1_kernel<<<dim3(N_ / 64, 1, B_), 256, AGG1_SMEM>>>(A);
    dense1_mma_kernel<<<dim3(BN / 64, HIDC / 128), 256, D1_SMEM>>>(b1);
    agg2_kernel<<<dim3(N_ / 128, HIDC / 128, B_), 256, AGG2_SMEM>>>();
    dense2_mma_kernel<<<BN / 128, 256, D2_SMEM>>>(b2, out, write_raw);
}

// round 17
// speedup vs baseline: 1.5432x; 1.0108x over previous
#include <cuda_runtime.h>
#include <cuda_bf16.h>
#include <cuda_fp16.h>
#include <cstdint>
#include <cstddef>

// Problem constants
constexpr int B_ = 8;
constexpr int N_ = 2048;
constexpr int INC = 128;
constexpr int HIDC = 256;
constexpr int OUTC = 32;
constexpr int BN = B_ * N_;

// Scratch (device globals: no allocation allowed)
__device__ __align__(16) float g_deg_inv[BN];
__device__ __align__(16) __nv_bfloat16 g_agg_hi[(size_t)BN * HIDC];  // row-major
__device__ __align__(16) __nv_bfloat16 g_agg_lo[(size_t)BN * HIDC];
__device__ __align__(16) __nv_bfloat16 g_h_hi[(size_t)BN * HIDC];    // row-major
__device__ __align__(16) __nv_bfloat16 g_h_lo[(size_t)BN * HIDC];
__device__ __align__(16) __nv_bfloat16 g_x_hi[(size_t)BN * INC];     // row-major
__device__ __align__(16) __nv_bfloat16 g_x_lo[(size_t)BN * INC];
// layer1: x^T fp16 single; layer2: reused as h^T fp16 single  [b][d][i]
__device__ __align__(16) __half g_T16[(size_t)B_ * HIDC * N_];
// Bit-packed mask: [b][it(32)][j(2048)][iq(4)] uint16 (i = it*64 + iq*16 .. +15)
__device__ __align__(16) uint16_t g_Mbits[(size_t)B_ * 32 * N_ * 4];
__device__ __align__(16) __nv_bfloat16 g_W1t_hi[2 * HIDC * INC];   // [mtx][n][k]
__device__ __align__(16) __nv_bfloat16 g_W1t_lo[2 * HIDC * INC];
__device__ __align__(16) __nv_bfloat16 g_W2t_hi[2 * OUTC * HIDC];
__device__ __align__(16) __nv_bfloat16 g_W2t_lo[2 * OUTC * HIDC];

#define SWZ(off) ((off) ^ (((off) >> 3) & 0x70))

__device__ __forceinline__ uint32_t smem_u32(const void* p) {
    uint32_t a;
    asm("{ .reg .u64 t; cvta.to.shared.u64 t, %1; cvt.u32.u64 %0, t; }"
        : "=r"(a) : "l"(p));
    return a;
}
__device__ __forceinline__ void cpa16(uint32_t dst, const void* src) {
    asm volatile("cp.async.cg.shared.global [%0], [%1], 16;" :: "r"(dst), "l"(src));
}
__device__ __forceinline__ void ldsm4(uint32_t* r, uint32_t addr) {
    asm volatile("ldmatrix.sync.aligned.m8n8.x4.shared.b16 {%0,%1,%2,%3}, [%4];"
                 : "=r"(r[0]), "=r"(r[1]), "=r"(r[2]), "=r"(r[3]) : "r"(addr));
}
__device__ __forceinline__ void mma_bf16(float* c, const uint32_t* a,
                                         uint32_t b0, uint32_t b1) {
    asm volatile(
        "mma.sync.aligned.m16n8k16.row.col.f32.bf16.bf16.f32 "
        "{%0,%1,%2,%3}, {%4,%5,%6,%7}, {%8,%9}, {%0,%1,%2,%3};"
        : "+f"(c[0]), "+f"(c[1]), "+f"(c[2]), "+f"(c[3])
        : "r"(a[0]), "r"(a[1]), "r"(a[2]), "r"(a[3]), "r"(b0), "r"(b1));
}
__device__ __forceinline__ void mma_f16(float* c, const uint32_t* a,
                                        uint32_t b0, uint32_t b1) {
    asm volatile(
        "mma.sync.aligned.m16n8k16.row.col.f32.f16.f16.f32 "
        "{%0,%1,%2,%3}, {%4,%5,%6,%7}, {%8,%9}, {%0,%1,%2,%3};"
        : "+f"(c[0]), "+f"(c[1]), "+f"(c[2]), "+f"(c[3])
        : "r"(a[0]), "r"(a[1]), "r"(a[2]), "r"(a[3]), "r"(b0), "r"(b1));
}
__device__ __forceinline__ void split2(float v0, float v1, uint32_t& hw, uint32_t& lw) {
    __nv_bfloat16 h0 = __float2bfloat16(v0);
    __nv_bfloat16 h1 = __float2bfloat16(v1);
    __nv_bfloat16 l0 = __float2bfloat16(v0 - __bfloat162float(h0));
    __nv_bfloat16 l1 = __float2bfloat16(v1 - __bfloat162float(h1));
    __nv_bfloat162 hp; hp.x = h0; hp.y = h1;
    __nv_bfloat162 lp; lp.x = l0; lp.y = l1;
    hw = *reinterpret_cast<uint32_t*>(&hp);
    lw = *reinterpret_cast<uint32_t*>(&lp);
}
// bits pair {b0,b1} (lowest 2 bits of v) -> fp16x2 {0,1} values
__device__ __forceinline__ uint32_t pairbits(uint32_t v) {
    return ((v & 1u) | ((v & 2u) << 15)) * 0x3C00u;
}
// Build m16n8k16 A-fragment (4 regs) for k-block kk from two 64-bit bit-rows.
// wr0 = bits of row r (16 bits per k16 block), wr1 = row r+8; c0 = (lane&3)*2.
__device__ __forceinline__ void frag_from_bits(uint32_t* a, uint2 wr0, uint2 wr1,
                                               int kk, int c0) {
    uint32_t s0 = ((kk & 2) ? wr0.y : wr0.x) >> (((kk & 1) << 4) + c0);
    uint32_t s1 = ((kk & 2) ? wr1.y : wr1.x) >> (((kk & 1) << 4) + c0);
    a[0] = pairbits(s0);
    a[1] = pairbits(s1);
    a[2] = pairbits(s0 >> 8);
    a[3] = pairbits(s1 >> 8);
}

// ---------------------------------------------------------------------------
// Merged prep: z < 8: x transpose->fp16 + row-major bf16 hi/lo; z == 8: weights.
// ---------------------------------------------------------------------------
__global__ __launch_bounds__(256)
void prep_kernel(const float* __restrict__ src,
                 const float* __restrict__ W1l, const float* __restrict__ W1r,
                 const float* __restrict__ W2l, const float* __restrict__ W2r) {
    constexpr int C = INC;
    if (blockIdx.z == 8) {
        int base = (blockIdx.x * 2 + blockIdx.y) * 256 + threadIdx.x;
#pragma unroll 1
        for (int idx = base; idx < 2 * HIDC * INC + 2 * OUTC * HIDC; idx += 16384) {
            float v;
            __nv_bfloat16 *hi, *lo;
            int off;
            if (idx < 2 * HIDC * INC) {
                int mtx = idx >> 15, rem = idx & 32767;
                int n = rem >> 7, k = rem & 127;
                v = (mtx ? W1r : W1l)[k * HIDC + n];
                hi = g_W1t_hi; lo = g_W1t_lo; off = idx;
            } else {
                int j = idx - 2 * HIDC * INC;
                int mtx = j >> 13, rem = j & 8191;
                int n = rem >> 8, k = rem & 255;
                v = (mtx ? W2r : W2l)[k * OUTC + n];
                hi = g_W2t_hi; lo = g_W2t_lo; off = j;
            }
            __nv_bfloat16 h = __float2bfloat16(v);
            hi[off] = h;
            lo[off] = __float2bfloat16(v - __bfloat162float(h));
        }
        return;
    }

    __shared__ float sT[64][65];
    const int t = threadIdx.x;
    const int b = blockIdx.z, i0 = blockIdx.x * 64, d0 = blockIdx.y * 64;

#pragma unroll
    for (int p = 0; p < 4; ++p) {
        int e = t + p * 256;
        int row = e >> 4, c4 = e & 15;
        size_t goff = ((size_t)(b * N_ + i0 + row)) * C + d0 + c4 * 4;
        float4 v = *reinterpret_cast<const float4*>(src + goff);
        sT[row][c4 * 4 + 0] = v.x; sT[row][c4 * 4 + 1] = v.y;
        sT[row][c4 * 4 + 2] = v.z; sT[row][c4 * 4 + 3] = v.w;
        uint32_t h0, l0, h1, l1;
        split2(v.x, v.y, h0, l0);
        split2(v.z, v.w, h1, l1);
        *reinterpret_cast<uint2*>(g_x_hi + goff) = make_uint2(h0, h1);
        *reinterpret_cast<uint2*>(g_x_lo + goff) = make_uint2(l0, l1);
    }
    __syncthreads();

    const int d = t >> 2, ic = (t & 3) * 16;
    uint32_t hb[8];
#pragma unroll
    for (int q = 0; q < 8; ++q) {
        __half2 hp = __floats2half2_rn(sT[ic + q * 2][d], sT[ic + q * 2 + 1][d]);
        hb[q] = *reinterpret_cast<uint32_t*>(&hp);
    }
    size_t obase = ((size_t)(b * C + d0 + d)) * N_ + i0 + ic;
    reinterpret_cast<uint4*>(g_T16 + obase)[0] = make_uint4(hb[0], hb[1], hb[2], hb[3]);
    reinterpret_cast<uint4*>(g_T16 + obase)[1] = make_uint4(hb[4], hb[5], hb[6], hb[7]);
}

// ---------------------------------------------------------------------------
// agg1 v8: register-built A-fragments from bits. maskconv stores only a
// uint16/thread to smem bits (+gmem bits for agg2). 3-stage, single barrier.
// CTA 64j x 128d; stage = 512 B bits + 16 KB X = 16896 B.
// ---------------------------------------------------------------------------
__global__ __launch_bounds__(256, 2)
void agg1_kernel(const int* __restrict__ A) {
    extern __shared__ __align__(1024) char smem[];
    constexpr int C = INC;
    constexpr int NIT = N_ / 64;
    constexpr int STG = 16896;  // bits 512 B | X 16 KB
    const int tid = threadIdx.x, lane = tid & 31, wid = tid >> 5;
    const int b = blockIdx.z, jt = blockIdx.x, j0 = jt * 64;
    const int jw = wid & 1, dw = wid >> 1;
    const int c0 = (lane & 3) * 2;
    const uint32_t sb = smem_u32(smem);
    float* sdeg = reinterpret_cast<float*>(smem + 3 * STG);

    if (tid < 64) sdeg[tid] = 0.0f;

    float acc[2][4][4];
#pragma unroll
    for (int mg = 0; mg < 2; ++mg)
#pragma unroll
        for (int ng = 0; ng < 4; ++ng)
#pragma unroll
            for (int q = 0; q < 4; ++q) acc[mg][ng][q] = 0.0f;

    const int jj = tid & 63, iq = tid >> 6;  // iq: 16 i's each
    const int* Ap = A + (size_t)b * N_ * N_ + j0 + jj;
    float degloc = 0.0f;

    auto maskconv = [&](int it) {
        const int i0 = it * 64;
        uint32_t bits = 0;
#pragma unroll
        for (int r = 0; r < 8; ++r) {
            int il = iq * 16 + r * 2;
            uint32_t b0 = Ap[(size_t)(i0 + il) * N_] ? 1u : 0u;
            uint32_t b1 = Ap[(size_t)(i0 + il + 1) * N_] ? 1u : 0u;
            bits |= (b0 << (r * 2)) | (b1 << (r * 2 + 1));
            degloc += (float)(b0 + b1);
        }
        // smem bits: [stage][j(64)][iq(4)] uint16
        *reinterpret_cast<uint16_t*>(
            smem + (it % 3) * STG + jj * 8 + iq * 2) = (uint16_t)bits;
        // gmem bits: [b][it][j][iq]
        g_Mbits[(((size_t)(b * 32 + it)) * N_ + j0 + jj) * 4 + iq] = (uint16_t)bits;
    };
    auto issueX = [&](int it) {
        const int i0 = it * 64;
#pragma unroll
        for (int p = 0; p < 4; ++p) {
            int idx = tid + p * 256;
            int row = idx >> 3, c = idx & 7;
            cpa16(sb + (it % 3) * STG + 512 + SWZ((uint32_t)(row * 128 + c * 16)),
                  g_T16 + ((size_t)(b * C + row)) * N_ + i0 + c * 8);
        }
        asm volatile("cp.async.commit_group;");
    };

    maskconv(0); issueX(0);
    maskconv(1); issueX(1);

#pragma unroll 1
    for (int it = 0; it < NIT; ++it) {
        if (it + 1 < NIT) {
            asm volatile("cp.async.wait_group 1;");
        } else {
            asm volatile("cp.async.wait_group 0;");
        }
        __syncthreads();  // single barrier per iteration

        if (it + 2 < NIT) { maskconv(it + 2); issueX(it + 2); }

        const char* bitsb = smem + (it % 3) * STG;
        const uint32_t xbase = sb + (it % 3) * STG + 512;

        uint2 wr[2][2];
#pragma unroll
        for (int mg = 0; mg < 2; ++mg) {
            int j1 = jw * 32 + mg * 16 + (lane >> 2);
            wr[mg][0] = *reinterpret_cast<const uint2*>(bitsb + j1 * 8);
            wr[mg][1] = *reinterpret_cast<const uint2*>(bitsb + (j1 + 8) * 8);
        }
#pragma unroll
        for (int kk = 0; kk < 4; ++kk) {
            uint32_t a[2][4];
#pragma unroll
            for (int mg = 0; mg < 2; ++mg)
                frag_from_bits(a[mg], wr[mg][0], wr[mg][1], kk, c0);
            uint32_t bf[2][4];
#pragma unroll
            for (int ng = 0; ng < 2; ++ng) {
                int rowB = dw * 32 + ng * 16 + (lane & 7) + ((lane >> 4) << 3);
                uint32_t addr = xbase + SWZ((uint32_t)(
                    rowB * 128 + kk * 32 + ((lane >> 3) & 1) * 16));
                ldsm4(bf[ng], addr);
            }
#pragma unroll
            for (int mg = 0; mg < 2; ++mg)
#pragma unroll
                for (int ng = 0; ng < 2; ++ng)
#pragma unroll
                    for (int sub = 0; sub < 2; ++sub)
                        mma_f16(acc[mg][ng * 2 + sub], a[mg],
                                bf[ng][sub * 2], bf[ng][sub * 2 + 1]);
        }
    }

    __syncthreads();
    atomicAdd(&sdeg[jj], degloc);
    __syncthreads();
    if (tid < 64) {
        float dinv = 1.0f / fmaxf(sdeg[tid], 1.0f);
        g_deg_inv[b * N_ + j0 + tid] = dinv;
        sdeg[tid] = dinv;
    }
    __syncthreads();

#pragma unroll
    for (int mg = 0; mg < 2; ++mg) {
        int jl0 = jw * 32 + mg * 16 + (lane >> 2);
        float dv0 = sdeg[jl0], dv1 = sdeg[jl0 + 8];
#pragma unroll
        for (int ng = 0; ng < 4; ++ng) {
            int d = dw * 32 + ng * 8 + (lane & 3) * 2;
            size_t ro = ((size_t)(b * N_ + j0 + jl0)) * C + d;
            uint32_t hw, lw;
            split2(acc[mg][ng][0] * dv0, acc[mg][ng][1] * dv0, hw, lw);
            *reinterpret_cast<uint32_t*>(g_agg_hi + ro) = hw;
            *reinterpret_cast<uint32_t*>(g_agg_lo + ro) = lw;
            split2(acc[mg][ng][2] * dv1, acc[mg][ng][3] * dv1, hw, lw);
            *reinterpret_cast<uint32_t*>(g_agg_hi + ro + (size_t)8 * C) = hw;
            *reinterpret_cast<uint32_t*>(g_agg_lo + ro + (size_t)8 * C) = lw;
        }
    }
}

// ---------------------------------------------------------------------------
// agg2 v8: CTA-resident bits (32 KB, preloaded once) + register-built
// A-fragments (no mask smem at all). X double-buffered. CTA 128j x 128d.
// smem: [0,32K) bits [it(32)][j(128)][8B]; [32K,+32K) X bufs.
// ---------------------------------------------------------------------------
__global__ __launch_bounds__(256, 2)
void agg2_kernel() {
    extern __shared__ __align__(1024) char smem[];
    constexpr int C = HIDC;
    constexpr int NIT = N_ / 64;
    constexpr uint32_t XOFF = 32768;
    const int tid = threadIdx.x, lane = tid & 31, wid = tid >> 5;
    const int b = blockIdx.z, j0 = blockIdx.x * 128;
    const int d0 = blockIdx.y * 128;
    const int jw = wid & 3, dw = wid >> 2;
    const int c0 = (lane & 3) * 2;
    const uint32_t sb = smem_u32(smem);

    float acc[2][8][4];
#pragma unroll
    for (int mg = 0; mg < 2; ++mg)
#pragma unroll
        for (int ng = 0; ng < 8; ++ng)
#pragma unroll
            for (int q = 0; q < 4; ++q) acc[mg][ng][q] = 0.0f;

    // ---- preload CTA's bit mask: 32 its x 128 j x 8 B = 32 KB ----
    {
        const char* Mb = reinterpret_cast<const char*>(g_Mbits) +
                         ((size_t)(b * 32) * N_ + j0) * 8;
#pragma unroll
        for (int p = 0; p < 8; ++p) {
            int idx = tid + p * 256;       // 2048 chunks of 16 B
            int it = idx >> 6, c = idx & 63;
            cpa16(sb + it * 1024 + c * 16, Mb + (size_t)it * (N_ * 8) + c * 16);
        }
        asm volatile("cp.async.commit_group;");
    }

    auto issueX = [&](int stage, int it) {
        const int i0 = it * 64;
#pragma unroll
        for (int p = 0; p < 4; ++p) {
            int idx = tid + p * 256;
            int row = idx >> 3, c = idx & 7;
            cpa16(sb + XOFF + stage * 16384 + SWZ((uint32_t)(row * 128 + c * 16)),
                  g_T16 + ((size_t)(b * C + d0 + row)) * N_ + i0 + c * 8);
        }
        asm volatile("cp.async.commit_group;");
    };

    issueX(0, 0);
    issueX(1, 1);
    // pending: {bits, X0, X1}

#pragma unroll 1
    for (int it = 0; it < NIT; ++it) {
        if (it + 1 < NIT) {
            asm volatile("cp.async.wait_group 1;");   // at it=0: bits+X0 done
        } else {
            asm volatile("cp.async.wait_group 0;");
        }
        __syncthreads();

        const char* bitsb = smem + it * 1024;
        const uint32_t xbase = sb + XOFF + (it & 1) * 16384;

        uint2 wr[2][2];
#pragma unroll
        for (int mg = 0; mg < 2; ++mg) {
            int j1 = jw * 32 + mg * 16 + (lane >> 2);
            wr[mg][0] = *reinterpret_cast<const uint2*>(bitsb + j1 * 8);
            wr[mg][1] = *reinterpret_cast<const uint2*>(bitsb + (j1 + 8) * 8);
        }
#pragma unroll
        for (int kk = 0; kk < 4; ++kk) {
            uint32_t a[2][4];
#pragma unroll
            for (int mg = 0; mg < 2; ++mg)
                frag_from_bits(a[mg], wr[mg][0], wr[mg][1], kk, c0);
            uint32_t bf[4][4];
#pragma unroll
            for (int ng = 0; ng < 4; ++ng) {
                int rowB = dw * 64 + ng * 16 + (lane & 7) + ((lane >> 4) << 3);
                uint32_t addr = xbase + SWZ((uint32_t)(
                    rowB * 128 + kk * 32 + ((lane >> 3) & 1) * 16));
                ldsm4(bf[ng], addr);
            }
#pragma unroll
            for (int mg = 0; mg < 2; ++mg)
#pragma unroll
                for (int ng = 0; ng < 4; ++ng)
#pragma unroll
                    for (int sub = 0; sub < 2; ++sub)
                        mma_f16(acc[mg][ng * 2 + sub], a[mg],
                                bf[ng][sub * 2], bf[ng][sub * 2 + 1]);
        }
        __syncthreads();   // all reads of X buf (it&1) complete
        if (it + 2 < NIT) issueX((it + 2) & 1, it + 2);  // safe: after sync
    }

#pragma unroll
    for (int mg = 0; mg < 2; ++mg) {
        int jl0 = jw * 32 + mg * 16 + (lane >> 2);
        float dv0 = g_deg_inv[b * N_ + j0 + jl0];
        float dv1 = g_deg_inv[b * N_ + j0 + jl0 + 8];
#pragma unroll
        for (int ng = 0; ng < 8; ++ng) {
            int d = d0 + dw * 64 + ng * 8 + (lane & 3) * 2;
            size_t ro = ((size_t)(b * N_ + j0 + jl0)) * C + d;
            uint32_t hw, lw;
            split2(acc[mg][ng][0] * dv0, acc[mg][ng][1] * dv0, hw, lw);
            *reinterpret_cast<uint32_t*>(g_agg_hi + ro) = hw;
            *reinterpret_cast<uint32_t*>(g_agg_lo + ro) = lw;
            split2(acc[mg][ng][2] * dv1, acc[mg][ng][3] * dv1, hw, lw);
            *reinterpret_cast<uint32_t*>(g_agg_hi + ro + (size_t)8 * C) = hw;
            *reinterpret_cast<uint32_t*>(g_agg_lo + ro + (size_t)8 * C) = lw;
        }
    }
}

// ---------------------------------------------------------------------------
// Dense1: per-64K-chunk {A_hi, A_lo, W_hi, W_lo}; 3 MMA combos; 4 stages.
// Epilogue: h row-major bf16 hi/lo + h^T fp16 single.
// ---------------------------------------------------------------------------
__global__ __launch_bounds__(256, 2)
void dense1_mma_kernel(const float* __restrict__ b1) {
    extern __shared__ __align__(1024) char smem[];
    constexpr int STG = 49152;  // Ah 8K | Al 8K | Bh 16K | Bl 16K
    const int tid = threadIdx.x, lane = tid & 31, wid = tid >> 5;
    const int mw = wid & 1, nw = wid >> 1;
    const int r0 = blockIdx.x * 64, c0 = blockIdx.y * 128;
    const int b = r0 >> 11, i0 = r0 & (N_ - 1);
    const uint32_t sb = smem_u32(smem);

    float acc[2][4][4];
#pragma unroll
    for (int mg = 0; mg < 2; ++mg)
#pragma unroll
        for (int nq = 0; nq < 4; ++nq)
#pragma unroll
            for (int q = 0; q < 4; ++q) acc[mg][nq][q] = 0.0f;

    auto load_stage = [&](int st, int sidx) {
        const int part = sidx >> 1, kb = (sidx & 1) * 64;
        const __nv_bfloat16* Ah = part ? g_x_hi : g_agg_hi;
        const __nv_bfloat16* Al = part ? g_x_lo : g_agg_lo;
        const __nv_bfloat16* Bh = g_W1t_hi + part * HIDC * INC;
        const __nv_bfloat16* Bl = g_W1t_lo + part * HIDC * INC;
#pragma unroll
        for (int p = 0; p < 4; ++p) {
            int idx = tid + p * 256;
            int r = idx >> 3, c = idx & 7;
            int hl = r >> 6, row = r & 63;
            cpa16(sb + st * STG + hl * 8192 + SWZ((uint32_t)(row * 128 + c * 16)),
                  (hl ? Al : Ah) + (size_t)(r0 + row) * INC + kb + c * 8);
        }
#pragma unroll
        for (int p = 0; p < 8; ++p) {
            int idx = tid + p * 256;
            int r = idx >> 3, c = idx & 7;
            int hl = r >> 7, row = r & 127;
            cpa16(sb + st * STG + 16384 + hl * 16384 +
                      SWZ((uint32_t)(row * 128 + c * 16)),
                  (hl ? Bl : Bh) + (size_t)(c0 + row) * INC + kb + c * 8);
        }
        asm volatile("cp.async.commit_group;");
    };

    load_stage(0, 0);

#pragma unroll 1
    for (int s = 0; s < 4; ++s) {
        const int cur = s & 1;
        if (s + 1 < 4) {
            load_stage(cur ^ 1, s + 1);
            asm volatile("cp.async.wait_group 1;");
        } else {
            asm volatile("cp.async.wait_group 0;");
        }
        __syncthreads();

        const uint32_t ahb = sb + cur * STG;
        const uint32_t alb = ahb + 8192;
        const uint32_t bhb = ahb + 16384;
        const uint32_t blb = ahb + 32768;
#pragma unroll
        for (int kk = 0; kk < 4; ++kk) {
            uint32_t ah[2][4], al[2][4];
#pragma unroll
            for (int mg = 0; mg < 2; ++mg) {
                uint32_t off = SWZ((uint32_t)(
                    (mw * 32 + mg * 16 + (lane & 15)) * 128 +
                    kk * 32 + (lane >> 4) * 16));
                ldsm4(ah[mg], ahb + off);
                ldsm4(al[mg], alb + off);
            }
            uint32_t bh[2][4], bl[2][4];
#pragma unroll
            for (int ng = 0; ng < 2; ++ng) {
                int rowB = nw * 32 + ng * 16 + (lane & 7) + ((lane >> 4) << 3);
                uint32_t off = SWZ((uint32_t)(
                    rowB * 128 + kk * 32 + ((lane >> 3) & 1) * 16));
                ldsm4(bh[ng], bhb + off);
                ldsm4(bl[ng], blb + off);
            }
#pragma unroll
            for (int mg = 0; mg < 2; ++mg)
#pragma unroll
                for (int ng = 0; ng < 2; ++ng)
#pragma unroll
                    for (int sub = 0; sub < 2; ++sub) {
                        float* c = acc[mg][ng * 2 + sub];
                        mma_bf16(c, ah[mg], bh[ng][sub * 2], bh[ng][sub * 2 + 1]);
                        mma_bf16(c, al[mg], bh[ng][sub * 2], bh[ng][sub * 2 + 1]);
                        mma_bf16(c, ah[mg], bl[ng][sub * 2], bl[ng][sub * 2 + 1]);
                    }
        }
        __syncthreads();
    }

#pragma unroll
    for (int mg = 0; mg < 2; ++mg) {
#pragma unroll
        for (int nq = 0; nq < 4; ++nq) {
            int dloc = nw * 32 + nq * 8 + (lane & 3) * 2;
            float2 bv = *reinterpret_cast<const float2*>(b1 + c0 + dloc);
            acc[mg][nq][0] = fmaxf(acc[mg][nq][0] + bv.x, 0.0f);
            acc[mg][nq][1] = fmaxf(acc[mg][nq][1] + bv.y, 0.0f);
            acc[mg][nq][2] = fmaxf(acc[mg][nq][2] + bv.x, 0.0f);
            acc[mg][nq][3] = fmaxf(acc[mg][nq][3] + bv.y, 0.0f);
            size_t ro = ((size_t)(r0 + mw * 32 + mg * 16 + (lane >> 2))) * HIDC +
                        c0 + dloc;
            uint32_t hw, lw;
            split2(acc[mg][nq][0], acc[mg][nq][1], hw, lw);
            *reinterpret_cast<uint32_t*>(g_h_hi + ro) = hw;
            *reinterpret_cast<uint32_t*>(g_h_lo + ro) = lw;
            split2(acc[mg][nq][2], acc[mg][nq][3], hw, lw);
            *reinterpret_cast<uint32_t*>(g_h_hi + ro + (size_t)8 * HIDC) = hw;
            *reinterpret_cast<uint32_t*>(g_h_lo + ro + (size_t)8 * HIDC) = lw;
        }
    }

    // single-pass transpose, fp16 single h^T
    float* sT = reinterpret_cast<float*>(smem);  // [64][129]
#pragma unroll
    for (int mg = 0; mg < 2; ++mg)
#pragma unroll
        for (int nq = 0; nq < 4; ++nq)
#pragma unroll
            for (int q = 0; q < 4; ++q) {
                int irow = mw * 32 + mg * 16 + (lane >> 2) + (q >> 1) * 8;
                int dl = nw * 32 + nq * 8 + (lane & 3) * 2 + (q & 1);
                sT[irow * 129 + dl] = acc[mg][nq][q];
            }
    __syncthreads();

    const int dl = tid & 127, iq = (tid >> 7) * 32;
    uint32_t hb[16];
#pragma unroll
    for (int q = 0; q < 16; ++q) {
        __half2 hp = __floats2half2_rn(sT[(iq + q * 2) * 129 + dl],
                                       sT[(iq + q * 2 + 1) * 129 + dl]);
        hb[q] = *reinterpret_cast<uint32_t*>(&hp);
    }
    size_t ob = ((size_t)(b * HIDC + c0 + dl)) * N_ + i0 + iq;
#pragma unroll
    for (int q = 0; q < 4; ++q)
        reinterpret_cast<uint4*>(g_T16 + ob)[q] =
            make_uint4(hb[q * 4], hb[q * 4 + 1], hb[q * 4 + 2], hb[q * 4 + 3]);
}

// ---------------------------------------------------------------------------
// Dense2: per-chunk {A_hi, A_lo, W_hi, W_lo} with 3 combos; 8 stages.
// ---------------------------------------------------------------------------
__global__ __launch_bounds__(256, 2)
void dense2_mma_kernel(const float* __restrict__ b2, float* __restrict__ out,
                       int write_raw) {
    extern __shared__ __align__(1024) char smem[];
    constexpr int STG = 40960;  // Ah 16K | Al 16K | Bh 4K | Bl 4K
    const int tid = threadIdx.x, lane = tid & 31, wid = tid >> 5;
    const int r0 = blockIdx.x * 128;
    const uint32_t sb = smem_u32(smem);

    float acc[4][4];
#pragma unroll
    for (int t = 0; t < 4; ++t)
#pragma unroll
        for (int q = 0; q < 4; ++q) acc[t][q] = 0.0f;

    auto load_stage = [&](int st, int sidx) {
        const int part = sidx >> 2, kb = (sidx & 3) * 64;
        const __nv_bfloat16* Ah = part ? g_h_hi : g_agg_hi;
        const __nv_bfloat16* Al = part ? g_h_lo : g_agg_lo;
        const __nv_bfloat16* Bh = g_W2t_hi + part * OUTC * HIDC;
        const __nv_bfloat16* Bl = g_W2t_lo + part * OUTC * HIDC;
#pragma unroll
        for (int p = 0; p < 8; ++p) {
            int idx = tid + p * 256;
            int r = idx >> 3, c = idx & 7;
            int hl = r >> 7, row = r & 127;
            cpa16(sb + st * STG + hl * 16384 + SWZ((uint32_t)(row * 128 + c * 16)),
                  (hl ? Al : Ah) + (size_t)(r0 + row) * HIDC + kb + c * 8);
        }
#pragma unroll
        for (int p = 0; p < 2; ++p) {
            int idx = tid + p * 256;
            int r = idx >> 3, c = idx & 7;
            int hl = r >> 5, row = r & 31;
            cpa16(sb + st * STG + 32768 + hl * 4096 +
                      SWZ((uint32_t)(row * 128 + c * 16)),
                  (hl ? Bl : Bh) + (size_t)row * HIDC + kb + c * 8);
        }
        asm volatile("cp.async.commit_group;");
    };

    load_stage(0, 0);

#pragma unroll 1
    for (int s = 0; s < 8; ++s) {
        const int cur = s & 1;
        if (s + 1 < 8) {
            load_stage(cur ^ 1, s + 1);
            asm volatile("cp.async.wait_group 1;");
        } else {
            asm volatile("cp.async.wait_group 0;");
        }
        __syncthreads();

        const uint32_t ahb = sb + cur * STG;
        const uint32_t alb = ahb + 16384;
        const uint32_t bhb = ahb + 32768;
        const uint32_t blb = ahb + 36864;
#pragma unroll
        for (int kk = 0; kk < 4; ++kk) {
            uint32_t ah[4], al[4];
            {
                uint32_t off = SWZ((uint32_t)(
                    (wid * 16 + (lane & 15)) * 128 + kk * 32 + (lane >> 4) * 16));
                ldsm4(ah, ahb + off);
                ldsm4(al, alb + off);
            }
            uint32_t bh[2][4], bl[2][4];
#pragma unroll
            for (int ng = 0; ng < 2; ++ng) {
                int rowB = ng * 16 + (lane & 7) + ((lane >> 4) << 3);
                uint32_t off = SWZ((uint32_t)(
                    rowB * 128 + kk * 32 + ((lane >> 3) & 1) * 16));
                ldsm4(bh[ng], bhb + off);
                ldsm4(bl[ng], blb + off);
            }
#pragma unroll
            for (int ng = 0; ng < 2; ++ng)
#pragma unroll
                for (int sub = 0; sub < 2; ++sub) {
                    float* c = acc[ng * 2 + sub];
                    mma_bf16(c, ah, bh[ng][sub * 2], bh[ng][sub * 2 + 1]);
                    mma_bf16(c, al, bh[ng][sub * 2], bh[ng][sub * 2 + 1]);
                    mma_bf16(c, ah, bl[ng][sub * 2], bl[ng][sub * 2 + 1]);
                }
        }
        __syncthreads();
    }

    float* sOut = reinterpret_cast<float*>(smem);
    __syncthreads();
#pragma unroll
    for (int t = 0; t < 4; ++t) {
        int d = t * 8 + (lane & 3) * 2;
        float2 bv = *reinterpret_cast<const float2*>(b2 + d);
        int row = wid * 16 + (lane >> 2);
        sOut[row * 33 + d] = acc[t][0] + bv.x;
        sOut[row * 33 + d + 1] = acc[t][1] + bv.y;
        sOut[(row + 8) * 33 + d] = acc[t][2] + bv.x;
        sOut[(row + 8) * 33 + d + 1] = acc[t][3] + bv.y;
    }
    __syncthreads();

#pragma unroll 1
    for (int rit = 0; rit < 16; ++rit) {
        int row = rit * 8 + wid;
        float v = sOut[row * 33 + lane];
        float m = v;
#pragma unroll
        for (int o = 16; o > 0; o >>= 1)
            m = fmaxf(m, __shfl_xor_sync(0xffffffffu, m, o));
        float s = expf(v - m);
#pragma unroll
        for (int o = 16; o > 0; o >>= 1)
            s += __shfl_xor_sync(0xffffffffu, s, o);
        float lsm = v - m - logf(s);
        size_t gi = (size_t)(r0 + row) * OUTC + lane;
        out[gi] = lsm;
        if (write_raw) out[(size_t)BN * OUTC + gi] = v;
    }
}

// ---------------------------------------------------------------------------
extern "C" void kernel_launch(void* const* d_in, const int* in_sizes, int n_in,
                              void* d_out, int out_size) {
    const float* x   = (const float*)d_in[0];
    const int*   A   = (const int*)d_in[1];
    const float* W1l = (const float*)d_in[2];
    const float* W1r = (const float*)d_in[3];
    const float* b1  = (const float*)d_in[4];
    const float* W2l = (const float*)d_in[5];
    const float* W2r = (const float*)d_in[6];
    const float* b2  = (const float*)d_in[7];
    float* out = (float*)d_out;
    (void)in_sizes; (void)n_in;

    const int write_raw = (out_size >= 2 * BN * OUTC) ? 1 : 0;

    constexpr int AGG1_SMEM = 3 * 16896 + 256;  // 50944
    constexpr int AGG2_SMEM = 65536;            // bits 32K + X 32K
    constexpr int D1_SMEM = 2 * 49152;          // 98304
    constexpr int D2_SMEM = 2 * 40960;          // 81920
    cudaFuncSetAttribute(agg1_kernel,
                         cudaFuncAttributeMaxDynamicSharedMemorySize, AGG1_SMEM);
    cudaFuncSetAttribute(agg2_kernel,
                         cudaFuncAttributeMaxDynamicSharedMemorySize, AGG2_SMEM);
    cudaFuncSetAttribute(dense1_mma_kernel,
                         cudaFuncAttributeMaxDynamicSharedMemorySize, D1_SMEM);
    cudaFuncSetAttribute(dense2_mma_kernel,
                         cudaFuncAttributeMaxDynamicSharedMemorySize, D2_SMEM);

    prep_kernel<<<dim3(N_ / 64, INC / 64, B_ + 1), 256>>>(x, W1l, W1r, W2l, W2r);
    agg1_kernel<<<dim3(N_ / 64, 1, B_), 256, AGG1_SMEM>>>(A);
    dense1_mma_kernel<<<dim3(BN / 64, HIDC / 128), 256, D1_SMEM>>>(b1);
    agg2_kernel<<<dim3(N_ / 128, HIDC / 128, B_), 256, AGG2_SMEM>>>();
    dense2_mma_kernel<<<BN / 128, 256, D2_SMEM>>>(b2, out, write_raw);
}